// round 1
// baseline (speedup 1.0000x reference)
#include <cuda_runtime.h>
#include <math.h>
#include <stdint.h>

// Problem constants (fixed by the dataset)
#define BB 256
#define NN 768
#define HH 3072
#define NLAYER 19          // hidden VN/CN iterations
#define NSMAT 20           // S has 20 slices
#define CLIPV 0.999999f

// Sparsity capacities (actual: W_vn<=3, M_cn<=7, M_first<=7, W_out<=4, bm/cm/S = 1)
#define CAP_VN 4
#define CAP_CN 8
#define CAP_F  8
#define CAP_OUT 8
#define CAP_BM 4
#define CAP_CM 4
#define CAP_S  4

// ---------------- device scratch (static; no allocation) ----------------
__device__ int   g_f_idx[HH * CAP_F];
__device__ int   g_f_cnt[HH];

__device__ int   g_cn_idx[HH * CAP_CN];
__device__ int   g_cn_cnt[HH];

__device__ int   g_vn_idx[HH * CAP_VN];          // pattern shared across 19 layers
__device__ int   g_vn_cnt[HH];
__device__ float g_vn_val[NLAYER * HH * CAP_VN]; // per-layer values

__device__ int   g_out_idx[NN * CAP_OUT];
__device__ int   g_out_cnt[NN];
__device__ float g_out_val[NN * CAP_OUT];

__device__ int   g_bm_idx[HH * CAP_BM];
__device__ int   g_bm_cnt[HH];
__device__ float g_bm_val[HH * CAP_BM];

__device__ int   g_cm_idx[NN * CAP_CM];
__device__ int   g_cm_cnt[NN];
__device__ float g_cm_val[NN * CAP_CM];

__device__ int   g_s_idx[NSMAT * NN * CAP_S];
__device__ int   g_s_cnt[NSMAT * NN];
__device__ float g_s_val[NSMAT * NN * CAP_S];

__device__ float g_xT[NN * BB];          // x transposed: [n][b]
__device__ float g_T [NSMAT * NN * BB];  // T[l][n][b] = (llr @ S[l])[b][n]
__device__ float g_u [HH * BB];          // state: u = 2*atanh(clip(h)), layout [i][b]
__device__ float g_v [HH * BB];          // VN output (tanh), layout [i][b]

// ---------------- helpers ----------------
__device__ __forceinline__ float atanh2f(float x) {
    // 2*atanh(clip(x)) = ln((1+x)/(1-x)) = ln2*(log2(1+x) - log2(1-x))
    x = fminf(fmaxf(x, -CLIPV), CLIPV);
    return 0.69314718055994531f * (__log2f(1.0f + x) - __log2f(1.0f - x));
}

// warp-per-row ordered sparsify (deterministic order via ballot prefix)
__device__ __forceinline__ void row_sparsify_dev(
    const float* __restrict__ mat, int rows, int cols,
    int* __restrict__ idx, float* __restrict__ val, int* __restrict__ cnt, int cap)
{
    int w = (blockIdx.x * blockDim.x + threadIdx.x) >> 5;
    int lane = threadIdx.x & 31;
    if (w >= rows) return;
    const float* r = mat + (size_t)w * cols;
    int c = 0;
    for (int base = 0; base < cols; base += 32) {
        float x = r[base + lane];
        unsigned m = __ballot_sync(0xffffffffu, x != 0.0f);
        if (x != 0.0f) {
            int pos = c + __popc(m & ((1u << lane) - 1u));
            if (pos < cap) {
                idx[(size_t)w * cap + pos] = base + lane;
                if (val) val[(size_t)w * cap + pos] = x;
            }
        }
        c += __popc(m);
    }
    if (lane == 0) cnt[w] = (c < cap) ? c : cap;
}

// column sparsify via atomic append (coalesced reads)
__device__ __forceinline__ void col_sparsify_dev(
    const float* __restrict__ mat, int nmats, int rows, int cols,
    int* __restrict__ idx, float* __restrict__ val, int* __restrict__ cnt, int cap)
{
    size_t total = (size_t)nmats * rows * cols;
    for (size_t t = (size_t)blockIdx.x * blockDim.x + threadIdx.x; t < total;
         t += (size_t)gridDim.x * blockDim.x) {
        float x = mat[t];
        if (x != 0.0f) {
            int c = (int)(t % cols);
            int r = (int)((t / cols) % rows);
            int l = (int)(t / ((size_t)rows * cols));
            int col = l * cols + c;
            int pos = atomicAdd(&cnt[col], 1);
            if (pos < cap) {
                idx[(size_t)col * cap + pos] = r;
                val[(size_t)col * cap + pos] = x;
            }
        }
    }
}

// ---------------- kernels ----------------
__global__ void k_zero_cnts() {
    int t = blockIdx.x * blockDim.x + threadIdx.x;
    if (t < HH)        g_bm_cnt[t] = 0;
    if (t < NN)        g_cm_cnt[t] = 0;
    if (t < NSMAT * NN) g_s_cnt[t] = 0;
}

__global__ void k_sp_first(const float* __restrict__ m) { row_sparsify_dev(m, HH, NN, g_f_idx,  nullptr,  g_f_cnt,  CAP_F);  }
__global__ void k_sp_cn   (const float* __restrict__ m) { row_sparsify_dev(m, HH, HH, g_cn_idx, nullptr,  g_cn_cnt, CAP_CN); }
__global__ void k_sp_w0   (const float* __restrict__ m) { row_sparsify_dev(m, HH, HH, g_vn_idx, g_vn_val, g_vn_cnt, CAP_VN); }
__global__ void k_sp_out  (const float* __restrict__ m) { row_sparsify_dev(m, NN, HH, g_out_idx, g_out_val, g_out_cnt, CAP_OUT); }

__global__ void k_sp_bm(const float* __restrict__ m) { col_sparsify_dev(m, 1,     NN, HH, g_bm_idx, g_bm_val, g_bm_cnt, CAP_BM); }
__global__ void k_sp_cm(const float* __restrict__ m) { col_sparsify_dev(m, 1,     NN, NN, g_cm_idx, g_cm_val, g_cm_cnt, CAP_CM); }
__global__ void k_sp_s (const float* __restrict__ m) { col_sparsify_dev(m, NSMAT, NN, NN, g_s_idx,  g_s_val,  g_s_cnt,  CAP_S);  }

// gather W_vn values for layers 1..18 at layer-0's pattern
__global__ void k_gather_w(const float* __restrict__ W) {
    int t = blockIdx.x * blockDim.x + threadIdx.x;
    if (t >= (NLAYER - 1) * HH) return;
    int l = 1 + t / HH;
    int i = t % HH;
    int c = g_vn_cnt[i];
    for (int k = 0; k < c; k++) {
        int j = g_vn_idx[i * CAP_VN + k];
        g_vn_val[((size_t)l * HH + i) * CAP_VN + k] =
            W[(size_t)l * HH * HH + (size_t)i * HH + j];
    }
}

__global__ void k_transpose_x(const float* __restrict__ x) {
    int t = blockIdx.x * blockDim.x + threadIdx.x;
    if (t >= BB * NN) return;
    int b = t / NN, n = t % NN;
    g_xT[n * BB + b] = x[t];
}

// T[l][n][b] = sum_m llr[b][m] * S[l][m][n]   (sparse over S columns)
__global__ void k_compute_T() {
    int t = blockIdx.x * blockDim.x + threadIdx.x;
    if (t >= NSMAT * NN * BB) return;
    int b = t % BB;
    int ln = t / BB;
    int c = g_s_cnt[ln]; if (c > CAP_S) c = CAP_S;
    float acc = 0.0f;
    for (int k = 0; k < c; k++)
        acc += g_s_val[ln * CAP_S + k] * g_xT[g_s_idx[ln * CAP_S + k] * BB + b];
    g_T[t] = acc;
}

// fc0: u = 2*atanh(clip(cn_update(tanh(0.5*x), M_first)))
__global__ void k_first() {
    int t = blockIdx.x * blockDim.x + threadIdx.x;
    if (t >= HH * BB) return;
    int b = t % BB, i = t / BB;
    int c = g_f_cnt[i];
    float prod = 1.0f; int nz = 0;
    for (int k = 0; k < c; k++) {
        float v = tanhf(0.5f * g_xT[g_f_idx[i * CAP_F + k] * BB + b]);
        if (v != 0.0f) { prod *= v; nz++; }
    }
    g_u[t] = nz ? atanh2f(prod) : 0.0f;
}

// VN update: v = tanh(0.5*(sum_k W[i,j_k]*u[j_k] + bias[i]))
__global__ void k_vn(int l) {
    int t = blockIdx.x * blockDim.x + threadIdx.x;
    if (t >= HH * BB) return;
    int b = t % BB, i = t / BB;
    float acc = 0.0f;
    int c = g_vn_cnt[i];
    const float* val = &g_vn_val[((size_t)l * HH + i) * CAP_VN];
    for (int k = 0; k < c; k++)
        acc += val[k] * g_u[g_vn_idx[i * CAP_VN + k] * BB + b];
    int cb = g_bm_cnt[i]; if (cb > CAP_BM) cb = CAP_BM;
    const float* Tl = &g_T[(size_t)l * NN * BB];
    for (int k = 0; k < cb; k++)
        acc += g_bm_val[i * CAP_BM + k] * Tl[g_bm_idx[i * CAP_BM + k] * BB + b];
    g_v[t] = tanhf(0.5f * acc);
}

// CN update fused with next layer's 2*atanh(clip())
__global__ void k_cn() {
    int t = blockIdx.x * blockDim.x + threadIdx.x;
    if (t >= HH * BB) return;
    int b = t % BB, i = t / BB;
    int c = g_cn_cnt[i];
    float prod = 1.0f; int nz = 0;
    for (int k = 0; k < c; k++) {
        float v = g_v[g_cn_idx[i * CAP_CN + k] * BB + b];
        if (v != 0.0f) { prod *= v; nz++; }
    }
    g_u[t] = nz ? atanh2f(prod) : 0.0f;
}

// output: sigmoid(u @ W_out.T + T[19] @ channel_mask)
__global__ void k_out(float* __restrict__ out) {
    int t = blockIdx.x * blockDim.x + threadIdx.x;
    if (t >= BB * NN) return;
    int b = t / NN, n = t % NN;
    float acc = 0.0f;
    int c = g_out_cnt[n];
    for (int k = 0; k < c; k++)
        acc += g_out_val[n * CAP_OUT + k] * g_u[g_out_idx[n * CAP_OUT + k] * BB + b];
    int cc = g_cm_cnt[n]; if (cc > CAP_CM) cc = CAP_CM;
    const float* T19 = &g_T[(size_t)(NSMAT - 1) * NN * BB];
    for (int k = 0; k < cc; k++)
        acc += g_cm_val[n * CAP_CM + k] * T19[g_cm_idx[n * CAP_CM + k] * BB + b];
    out[t] = 1.0f / (1.0f + expf(-acc));
}

// ---------------- launch ----------------
extern "C" void kernel_launch(void* const* d_in, const int* in_sizes, int n_in,
                              void* d_out, int out_size) {
    const float* x    = (const float*)d_in[0];   // [B,N]
    const float* Wvn  = (const float*)d_in[1];   // [19,H,H]
    const float* Wout = (const float*)d_in[2];   // [N,H]
    const float* S    = (const float*)d_in[3];   // [20,N,N]
    const float* bm   = (const float*)d_in[4];   // [N,H]
    const float* cm   = (const float*)d_in[5];   // [N,N]
    const float* Mf   = (const float*)d_in[6];   // [H,N]
    const float* Mcn  = (const float*)d_in[7];   // [H,H]
    float* out = (float*)d_out;

    const int TB = 256;

    // 1) zero atomic counters
    k_zero_cnts<<<(NSMAT * NN + TB - 1) / TB, TB>>>();

    // 2) sparsify all structures
    k_sp_first<<<(HH * 32 + TB - 1) / TB, TB>>>(Mf);
    k_sp_cn   <<<(HH * 32 + TB - 1) / TB, TB>>>(Mcn);
    k_sp_w0   <<<(HH * 32 + TB - 1) / TB, TB>>>(Wvn);     // layer-0 pattern + values
    k_sp_out  <<<(NN * 32 + TB - 1) / TB, TB>>>(Wout);
    k_sp_bm   <<<2048, TB>>>(bm);
    k_sp_cm   <<<2048, TB>>>(cm);
    k_sp_s    <<<2048, TB>>>(S);

    // 3) gather remaining W_vn layer values at shared pattern
    k_gather_w<<<((NLAYER - 1) * HH + TB - 1) / TB, TB>>>(Wvn);

    // 4) transpose x; precompute all 20 bias tensors T[l] = llr @ S[l]
    k_transpose_x<<<(BB * NN + TB - 1) / TB, TB>>>(x);
    k_compute_T  <<<(NSMAT * NN * BB + TB - 1) / TB, TB>>>();

    // 5) forward pass
    const int gHB = (HH * BB + TB - 1) / TB;
    k_first<<<gHB, TB>>>();
    for (int l = 0; l < NLAYER; l++) {
        k_vn<<<gHB, TB>>>(l);
        k_cn<<<gHB, TB>>>();
    }
    k_out<<<(BB * NN + TB - 1) / TB, TB>>>(out);
}

// round 3
// speedup vs baseline: 1.7207x; 1.7207x over previous
#include <cuda_runtime.h>
#include <math.h>
#include <stdint.h>

// Problem constants (fixed by the dataset)
#define BB 256
#define NN 768
#define HH 3072
#define NLAYER 19          // hidden VN/CN iterations
#define NSMAT 20           // S has 20 slices
#define CLIPV 0.999999f

// Sparsity capacities (actual: W_vn<=3, M_cn<=7, M_first<=7, W_out<=4, bm/cm/S col = 1)
#define CAP_VN 3
#define CAP_CN 7
#define CAP_F  7
#define CAP_OUT 4
#define CAP_S  4

// ---------------- device scratch (static; no allocation) ----------------
__device__ unsigned short g_f_idx16 [CAP_F  * HH];   // pad -> NN (sentinel)
__device__ unsigned short g_cn_idx16[CAP_CN * HH];   // pad -> HH (sentinel)
__device__ unsigned short g_vn_idx16[CAP_VN * HH];   // pad -> 0 (val 0)
__device__ int            g_vn_cnt[HH];
__device__ float          g_vn_val[NLAYER][CAP_VN][HH]; // repacked, zero-padded
__device__ unsigned short g_out_idx16[CAP_OUT * NN]; // pad -> 0 (val 0)
__device__ float          g_out_val  [CAP_OUT * NN];
__device__ unsigned short g_bidx16[HH];
__device__ float          g_bval  [HH];
__device__ unsigned short g_cmidx16[NN];
__device__ float          g_cmval  [NN];

__device__ int   g_s_idx[NSMAT * NN * CAP_S];
__device__ int   g_s_cnt[NSMAT * NN];
__device__ float g_s_val[NSMAT * NN * CAP_S];

__device__ float g_T[NSMAT][BB][NN];   // T[l][b][n] = (llr @ S[l])[b][n]

// ---------------- helpers ----------------
__device__ __forceinline__ float atanh2f(float x) {
    // 2*atanh(clip(x)) = ln2*(log2(1+x) - log2(1-x))
    x = fminf(fmaxf(x, -CLIPV), CLIPV);
    return 0.69314718055994531f * (__log2f(1.0f + x) - __log2f(1.0f - x));
}
__device__ __forceinline__ float tanh_fast(float y) {
    // stable for all y: exp overflow -> inf -> result +/-1
    return 1.0f - 2.0f / (1.0f + __expf(2.0f * y));
}

// warp-per-row ordered sparsify, transposed 16-bit output [k][row], padded
template<int CAP>
__global__ void k_row_sp(const float* __restrict__ mat, int rows, int cols,
                         unsigned short* __restrict__ idx, float* __restrict__ val,
                         int* __restrict__ cnt, int padidx)
{
    int w = (blockIdx.x * blockDim.x + threadIdx.x) >> 5;
    int lane = threadIdx.x & 31;
    if (w >= rows) return;
    const float* r = mat + (size_t)w * cols;
    int c = 0;
    for (int base = 0; base < cols; base += 32) {
        float xv = r[base + lane];
        unsigned m = __ballot_sync(0xffffffffu, xv != 0.0f);
        if (xv != 0.0f) {
            int pos = c + __popc(m & ((1u << lane) - 1u));
            if (pos < CAP) {
                idx[pos * rows + w] = (unsigned short)(base + lane);
                if (val) val[pos * rows + w] = xv;
            }
        }
        c += __popc(m);
    }
    if (c > CAP) c = CAP;
    if (lane >= c && lane < CAP) {
        idx[lane * rows + w] = (unsigned short)padidx;
        if (val) val[lane * rows + w] = 0.0f;
    }
    if (cnt && lane == 0) cnt[w] = c;
}

// ---------------- setup kernels ----------------
__global__ void k_zero_cnts() {
    int t = blockIdx.x * blockDim.x + threadIdx.x;
    if (t < HH)         { g_bidx16[t] = 0; g_bval[t] = 0.0f; }
    if (t < NN)         { g_cmidx16[t] = 0; g_cmval[t] = 0.0f; }
    if (t < NSMAT * NN) g_s_cnt[t] = 0;
}

// bm [N,H]: exactly one nonzero per column h -> direct store
__global__ void k_sp_bm(const float* __restrict__ m) {
    for (int t = blockIdx.x * blockDim.x + threadIdx.x; t < NN * HH;
         t += gridDim.x * blockDim.x) {
        float x = m[t];
        if (x != 0.0f) {
            int col = t % HH, row = t / HH;
            g_bidx16[col] = (unsigned short)row;
            g_bval[col] = x;
        }
    }
}
// cm [N,N]: exactly one nonzero per column
__global__ void k_sp_cm(const float* __restrict__ m) {
    for (int t = blockIdx.x * blockDim.x + threadIdx.x; t < NN * NN;
         t += gridDim.x * blockDim.x) {
        float x = m[t];
        if (x != 0.0f) {
            int col = t % NN, row = t / NN;
            g_cmidx16[col] = (unsigned short)row;
            g_cmval[col] = x;
        }
    }
}
// S [20,N,N]: column sparsify with atomic append
__global__ void k_sp_s(const float* __restrict__ m) {
    size_t total = (size_t)NSMAT * NN * NN;
    for (size_t t = (size_t)blockIdx.x * blockDim.x + threadIdx.x; t < total;
         t += (size_t)gridDim.x * blockDim.x) {
        float x = m[t];
        if (x != 0.0f) {
            int c = (int)(t % NN);
            int r = (int)((t / NN) % NN);
            int l = (int)(t / ((size_t)NN * NN));
            int col = l * NN + c;
            int pos = atomicAdd(&g_s_cnt[col], 1);
            if (pos < CAP_S) {
                g_s_idx[col * CAP_S + pos] = r;
                g_s_val[col * CAP_S + pos] = x;
            }
        }
    }
}

// gather W_vn values for layers 1..18 at layer-0 pattern, zero-padded
__global__ void k_gather_w(const float* __restrict__ W) {
    int t = blockIdx.x * blockDim.x + threadIdx.x;
    if (t >= (NLAYER - 1) * CAP_VN * HH) return;
    int l = t / (CAP_VN * HH);
    int r = t % (CAP_VN * HH);
    int k = r / HH;
    int i = r % HH;
    float v = 0.0f;
    if (k < g_vn_cnt[i]) {
        int j = g_vn_idx16[k * HH + i];
        v = W[((size_t)(l + 1) * HH + i) * HH + j];
    }
    g_vn_val[l + 1][k][i] = v;
}

// T[l][b][n] = sum_m x[b][m] * S[l][m][n]
__global__ void k_compute_T(const float* __restrict__ x) {
    int t = blockIdx.x * blockDim.x + threadIdx.x;
    if (t >= NSMAT * BB * NN) return;
    int n = t % NN;
    int b = (t / NN) % BB;
    int l = t / (BB * NN);
    int ln = l * NN + n;
    int c = g_s_cnt[ln]; if (c > CAP_S) c = CAP_S;
    float acc = 0.0f;
    for (int k = 0; k < c; k++)
        acc += g_s_val[ln * CAP_S + k] * x[b * NN + g_s_idx[ln * CAP_S + k]];
    g_T[l][b][n] = acc;
}

// ---------------- fused forward: one block per batch element ----------------
#define FWD_TB 512
#define NODES_PER_T (HH / FWD_TB)   // 6

// dynamic smem layout (floats): su[HH], sv[HH+1], sw[NN+1], then u16 idx arrays
#define SM_FLTS (HH + HH + 1 + NN + 1)                 // 6914 floats
#define SM_IDX_BYTES ((CAP_CN + CAP_VN) * HH * 2)      // 61440
#define SM_TOTAL_BYTES (SM_FLTS * 4 + SM_IDX_BYTES)    // 89096

__global__ void __launch_bounds__(FWD_TB)
k_forward(const float* __restrict__ x, float* __restrict__ out) {
    extern __shared__ char smem[];
    float* su = (float*)smem;               // [HH]
    float* sv = su + HH;                    // [HH+1], sv[HH]=0 sentinel
    float* sw = sv + HH + 1;                // [NN+1], sw[NN]=0 sentinel
    unsigned short* scidx = (unsigned short*)(smem + SM_FLTS * 4);      // [CAP_CN][HH]
    unsigned short* svidx = scidx + CAP_CN * HH;                        // [CAP_VN][HH]

    const int b = blockIdx.x;
    const int t = threadIdx.x;

    // stage indices into smem (pattern shared across all layers)
    for (int z = t; z < CAP_CN * HH; z += FWD_TB) scidx[z] = g_cn_idx16[z];
    for (int z = t; z < CAP_VN * HH; z += FWD_TB) svidx[z] = g_vn_idx16[z];
    // channel tanh row
    for (int n = t; n < NN; n += FWD_TB) sw[n] = tanh_fast(0.5f * x[b * NN + n]);
    if (t == 0) { sw[NN] = 0.0f; sv[HH] = 0.0f; }

    // per-thread persistent bias regs
    unsigned short bi[NODES_PER_T];
    float bv[NODES_PER_T];
    #pragma unroll
    for (int q = 0; q < NODES_PER_T; q++) {
        int i = t + FWD_TB * q;
        bi[q] = g_bidx16[i];
        bv[q] = g_bval[i];
    }
    __syncthreads();

    // first CN: u = 2*atanh(clip(prod tanh(0.5 x) over M_first row))
    #pragma unroll
    for (int q = 0; q < NODES_PER_T; q++) {
        int i = t + FWD_TB * q;
        float prod = 1.0f; int nz = 0;
        #pragma unroll
        for (int k = 0; k < CAP_F; k++) {
            float v = sw[g_f_idx16[k * HH + i]];   // pad -> sw[NN]=0 -> skipped
            if (v != 0.0f) { prod *= v; nz++; }
        }
        su[i] = nz ? atanh2f(prod) : 0.0f;
    }
    __syncthreads();

    // 19 BP iterations
    for (int l = 0; l < NLAYER; l++) {
        // bias row for this layer
        for (int n = t; n < NN; n += FWD_TB) sw[n] = g_T[l][b][n];
        __syncthreads();

        // VN: v = tanh(0.5*(W u + bias))
        #pragma unroll
        for (int q = 0; q < NODES_PER_T; q++) {
            int i = t + FWD_TB * q;
            float acc = bv[q] * sw[bi[q]];
            #pragma unroll
            for (int k = 0; k < CAP_VN; k++)
                acc += g_vn_val[l][k][i] * su[svidx[k * HH + i]]; // pad val=0
            sv[i] = tanh_fast(0.5f * acc);
        }
        __syncthreads();

        // CN fused with next atanh: u = 2*atanh(clip(prod v over M_cn row))
        #pragma unroll
        for (int q = 0; q < NODES_PER_T; q++) {
            int i = t + FWD_TB * q;
            float prod = 1.0f; int nz = 0;
            #pragma unroll
            for (int k = 0; k < CAP_CN; k++) {
                float v = sv[scidx[k * HH + i]];   // pad -> sv[HH]=0 -> skipped
                if (v != 0.0f) { prod *= v; nz++; }
            }
            su[i] = nz ? atanh2f(prod) : 0.0f;
        }
        __syncthreads();
    }

    // output: sigmoid(u @ W_out.T + T[19] @ channel_mask)
    for (int n = t; n < NN; n += FWD_TB) sw[n] = g_T[NSMAT - 1][b][n];
    __syncthreads();
    for (int n = t; n < NN; n += FWD_TB) {
        float acc = g_cmval[n] * sw[g_cmidx16[n]];
        #pragma unroll
        for (int k = 0; k < CAP_OUT; k++)
            acc += g_out_val[k * NN + n] * su[g_out_idx16[k * NN + n]]; // pad val=0
        out[b * NN + n] = 1.0f / (1.0f + __expf(-acc));
    }
}

// ---------------- launch ----------------
extern "C" void kernel_launch(void* const* d_in, const int* in_sizes, int n_in,
                              void* d_out, int out_size) {
    const float* x    = (const float*)d_in[0];   // [B,N]
    const float* Wvn  = (const float*)d_in[1];   // [19,H,H]
    const float* Wout = (const float*)d_in[2];   // [N,H]
    const float* S    = (const float*)d_in[3];   // [20,N,N]
    const float* bm   = (const float*)d_in[4];   // [N,H]
    const float* cm   = (const float*)d_in[5];   // [N,N]
    const float* Mf   = (const float*)d_in[6];   // [H,N]
    const float* Mcn  = (const float*)d_in[7];   // [H,H]
    float* out = (float*)d_out;

    const int TB = 256;

    // opt-in smem (idempotent host-side attribute set; tolerate repeat calls)
    static bool s_attr_done = false;
    if (!s_attr_done) {
        cudaFuncSetAttribute(k_forward, cudaFuncAttributeMaxDynamicSharedMemorySize,
                             SM_TOTAL_BYTES);
        s_attr_done = true;
    }

    // 1) zero/default counters and single-entry tables
    k_zero_cnts<<<(NSMAT * NN + TB - 1) / TB, TB>>>();

    // 2) sparsify all structures (ordered, deterministic)
    k_row_sp<CAP_F>  <<<(HH * 32 + TB - 1) / TB, TB>>>(Mf,  HH, NN, g_f_idx16,  nullptr,            nullptr,  NN);
    k_row_sp<CAP_CN> <<<(HH * 32 + TB - 1) / TB, TB>>>(Mcn, HH, HH, g_cn_idx16, nullptr,            nullptr,  HH);
    k_row_sp<CAP_VN> <<<(HH * 32 + TB - 1) / TB, TB>>>(Wvn, HH, HH, g_vn_idx16, &g_vn_val[0][0][0], g_vn_cnt, 0);
    k_row_sp<CAP_OUT><<<(NN * 32 + TB - 1) / TB, TB>>>(Wout, NN, HH, g_out_idx16, g_out_val,        nullptr,  0);
    k_sp_bm<<<1024, TB>>>(bm);
    k_sp_cm<<<1024, TB>>>(cm);
    k_sp_s <<<2048, TB>>>(S);

    // 3) gather remaining W_vn layers at shared pattern (repacked [l][k][i])
    k_gather_w<<<((NLAYER - 1) * CAP_VN * HH + TB - 1) / TB, TB>>>(Wvn);

    // 4) precompute bias tensors T[l][b][n] = (llr @ S[l])
    k_compute_T<<<(NSMAT * BB * NN + TB - 1) / TB, TB>>>(x);

    // 5) fully fused forward pass: one block per batch element, state in smem
    k_forward<<<BB, FWD_TB, SM_TOTAL_BYTES>>>(x, out);
}

// round 6
// speedup vs baseline: 2.1029x; 1.2221x over previous
#include <cuda_runtime.h>
#include <math.h>
#include <stdint.h>

// Problem constants (fixed by the dataset)
#define BB 256
#define NN 768
#define HH 3072
#define NLAYER 19          // hidden VN/CN iterations
#define NSMAT 20           // S has 20 slices
#define CLIPV 0.999999f

// Sparsity capacities (actual: W_vn<=3, M_cn<=7, M_first<=7, W_out<=4, bm/cm/S col = 1)
#define CAP_VN 3
#define CAP_CN 7
#define CAP_F  7
#define CAP_OUT 4
#define CAP_S  4

// ---------------- device scratch (static; no allocation) ----------------
__device__ unsigned short g_f_idx16[CAP_F * HH];            // [k][i], pad -> NN
__device__ __align__(16) unsigned short g_cn_pack[HH * 8];  // [i][8], pad -> HH
__device__ __align__(8)  unsigned short g_vn_pack[HH * 4];  // [i][4]: j0,j1,j2,bias_idx
__device__ int            g_vn_cnt[HH];
__device__ float          g_vn_val[NLAYER][CAP_VN][HH];     // repacked, zero-padded
__device__ unsigned short g_out_idx16[CAP_OUT * NN];        // [k][n], pad -> 0 (val 0)
__device__ float          g_out_val  [CAP_OUT * NN];
__device__ float          g_bval  [HH];
__device__ unsigned short g_cmidx16[NN];
__device__ float          g_cmval  [NN];

__device__ int   g_s_idx[NSMAT * NN * CAP_S];
__device__ int   g_s_cnt[NSMAT * NN];
__device__ float g_s_val[NSMAT * NN * CAP_S];

__device__ float g_T[NSMAT][BB][NN];   // T[l][b][n] = (llr @ S[l])[b][n]

// ---------------- helpers ----------------
__device__ __forceinline__ float atanh2f(float x) {
    // 2*atanh(clip(x)) = ln2*(log2(1+x) - log2(1-x))
    x = fminf(fmaxf(x, -CLIPV), CLIPV);
    return 0.69314718055994531f * (__log2f(1.0f + x) - __log2f(1.0f - x));
}
__device__ __forceinline__ float tanh_fast(float y) {
    // stable for all y: exp overflow -> inf -> result +/-1
    return 1.0f - 2.0f / (1.0f + __expf(2.0f * y));
}

// float4-vectorized ordered row scan; emit(pos, col, val) for each nonzero.
template <class F>
__device__ __forceinline__ int scan_row_f4(const float* __restrict__ row,
                                           int cols, int lane, F emit) {
    const float4* r4 = reinterpret_cast<const float4*>(row);
    int c = 0;
    for (int base4 = 0; base4 < cols / 4; base4 += 32) {
        float4 v = r4[base4 + lane];
        float a0 = v.x, a1 = v.y, a2 = v.z, a3 = v.w;
        int col0 = (base4 + lane) * 4;
        #pragma unroll
        for (int s = 0; s < 4; s++) {
            float av = (s == 0) ? a0 : (s == 1) ? a1 : (s == 2) ? a2 : a3;
            unsigned m = __ballot_sync(0xffffffffu, av != 0.0f);
            if (av != 0.0f) {
                int pos = c + __popc(m & ((1u << lane) - 1u));
                emit(pos, col0 + s, av);
            }
            c += __popc(m);
        }
    }
    return c;
}

// ---------------- setup kernels ----------------
__global__ void k_zero() {
    int t = blockIdx.x * blockDim.x + threadIdx.x;
    if (t < HH)         { g_bval[t] = 0.0f; g_vn_pack[t * 4 + 3] = 0; }
    if (t < NN)         { g_cmidx16[t] = 0; g_cmval[t] = 0.0f; }
    if (t < NSMAT * NN) g_s_cnt[t] = 0;
}

// merged row scans: Mf | Mcn | Wvn layer0 | Wout, one warp per row
__global__ void k_scan_rows(const float* __restrict__ Mf,
                            const float* __restrict__ Mcn,
                            const float* __restrict__ Wvn,
                            const float* __restrict__ Wout) {
    int gw = (blockIdx.x * blockDim.x + threadIdx.x) >> 5;
    int lane = threadIdx.x & 31;

    if (gw < HH) {                                    // Mf [HH x NN]
        int w = gw;
        int c = scan_row_f4(Mf + (size_t)w * NN, NN, lane,
            [&](int p, int col, float) { if (p < CAP_F) g_f_idx16[p * HH + w] = (unsigned short)col; });
        if (c > CAP_F) c = CAP_F;
        if (lane >= c && lane < CAP_F) g_f_idx16[lane * HH + w] = (unsigned short)NN;
    } else if (gw < 2 * HH) {                         // Mcn [HH x HH]
        int w = gw - HH;
        int c = scan_row_f4(Mcn + (size_t)w * HH, HH, lane,
            [&](int p, int col, float) { if (p < CAP_CN) g_cn_pack[w * 8 + p] = (unsigned short)col; });
        if (c > CAP_CN) c = CAP_CN;
        if (lane >= c && lane < 8) g_cn_pack[w * 8 + lane] = (unsigned short)HH;
    } else if (gw < 3 * HH) {                         // Wvn layer 0 [HH x HH]
        int w = gw - 2 * HH;
        int c = scan_row_f4(Wvn + (size_t)w * HH, HH, lane,
            [&](int p, int col, float v) {
                if (p < CAP_VN) { g_vn_pack[w * 4 + p] = (unsigned short)col; g_vn_val[0][p][w] = v; } });
        if (c > CAP_VN) c = CAP_VN;
        if (lane >= c && lane < CAP_VN) { g_vn_pack[w * 4 + lane] = 0; g_vn_val[0][lane][w] = 0.0f; }
        if (lane == 0) g_vn_cnt[w] = c;
    } else if (gw < 3 * HH + NN) {                    // Wout [NN x HH]
        int w = gw - 3 * HH;
        int c = scan_row_f4(Wout + (size_t)w * HH, HH, lane,
            [&](int p, int col, float v) {
                if (p < CAP_OUT) { g_out_idx16[p * NN + w] = (unsigned short)col; g_out_val[p * NN + w] = v; } });
        if (c > CAP_OUT) c = CAP_OUT;
        if (lane >= c && lane < CAP_OUT) { g_out_idx16[lane * NN + w] = 0; g_out_val[lane * NN + w] = 0.0f; }
    }
}

// merged column scans: bm (1 nz/col), cm (1 nz/col), S (atomic append)
__global__ void k_scan_cols(const float* __restrict__ bm,
                            const float* __restrict__ cm,
                            const float* __restrict__ S) {
    int tid = blockIdx.x * blockDim.x + threadIdx.x;
    int stride = gridDim.x * blockDim.x;

    const float4* b4 = reinterpret_cast<const float4*>(bm);
    for (int t = tid; t < NN * HH / 4; t += stride) {
        float4 v = b4[t];
        float a[4] = {v.x, v.y, v.z, v.w};
        #pragma unroll
        for (int s = 0; s < 4; s++) if (a[s] != 0.0f) {
            int f = t * 4 + s, col = f % HH, row = f / HH;
            g_bval[col] = a[s];
            g_vn_pack[col * 4 + 3] = (unsigned short)row;   // bias idx in slot 3
        }
    }
    const float4* c4 = reinterpret_cast<const float4*>(cm);
    for (int t = tid; t < NN * NN / 4; t += stride) {
        float4 v = c4[t];
        float a[4] = {v.x, v.y, v.z, v.w};
        #pragma unroll
        for (int s = 0; s < 4; s++) if (a[s] != 0.0f) {
            int f = t * 4 + s, col = f % NN, row = f / NN;
            g_cmval[col] = a[s];
            g_cmidx16[col] = (unsigned short)row;
        }
    }
    const float4* s4 = reinterpret_cast<const float4*>(S);
    for (int t = tid; t < NSMAT * NN * NN / 4; t += stride) {
        float4 v = s4[t];
        float a[4] = {v.x, v.y, v.z, v.w};
        #pragma unroll
        for (int s = 0; s < 4; s++) if (a[s] != 0.0f) {
            int f = t * 4 + s;
            int c = f % NN, r = (f / NN) % NN, l = f / (NN * NN);
            int colI = l * NN + c;
            int pos = atomicAdd(&g_s_cnt[colI], 1);
            if (pos < CAP_S) { g_s_idx[colI * CAP_S + pos] = r; g_s_val[colI * CAP_S + pos] = a[s]; }
        }
    }
}

// gather W_vn values for layers 1..18 at layer-0 pattern, zero-padded
__global__ void k_gather_w(const float* __restrict__ W) {
    int t = blockIdx.x * blockDim.x + threadIdx.x;
    if (t >= (NLAYER - 1) * CAP_VN * HH) return;
    int l = t / (CAP_VN * HH) + 1;
    int r = t % (CAP_VN * HH);
    int k = r / HH;
    int i = r % HH;
    float v = 0.0f;
    if (k < g_vn_cnt[i]) {
        int j = g_vn_pack[i * 4 + k];
        v = W[((size_t)l * HH + i) * HH + j];
    }
    g_vn_val[l][k][i] = v;
}

// T[l][b][n] = sum_m x[b][m] * S[l][m][n]
__global__ void k_compute_T(const float* __restrict__ x) {
    int t = blockIdx.x * blockDim.x + threadIdx.x;
    if (t >= NSMAT * BB * NN) return;
    int n = t % NN;
    int b = (t / NN) % BB;
    int l = t / (BB * NN);
    int ln = l * NN + n;
    int c = g_s_cnt[ln]; if (c > CAP_S) c = CAP_S;
    float acc = 0.0f;
    for (int k = 0; k < c; k++)
        acc += g_s_val[ln * CAP_S + k] * x[b * NN + g_s_idx[ln * CAP_S + k]];
    g_T[l][b][n] = acc;
}

// ---------------- fused forward: one block per batch element ----------------
#define FWD_TB 512
#define NODES_PER_T (HH / FWD_TB)   // 6

// dynamic smem: uint4 cpk[HH] | uint2 vpk[HH] | su[HH] | sv[HH+1] | sw[NN]
#define SM_TOTAL_BYTES (HH * 16 + HH * 8 + (HH + HH + 1 + NN) * 4)   // 101380

__global__ void __launch_bounds__(FWD_TB)
k_forward(const float* __restrict__ x, float* __restrict__ out) {
    extern __shared__ char smem[];
    uint4* cpk = (uint4*)smem;                 // [HH] packed CN idx (8 u16)
    uint2* vpk = (uint2*)(cpk + HH);           // [HH] packed VN idx (3 u16 + bias idx)
    float* su = (float*)(vpk + HH);            // [HH]
    float* sv = su + HH;                       // [HH+1], sv[HH]=0 sentinel
    float* sw = sv + HH + 1;                   // [NN] bias row

    const int b = blockIdx.x;
    const int t = threadIdx.x;

    // stage packed indices (vectorized, L2-broadcast)
    const uint4* gc = (const uint4*)g_cn_pack;
    const uint2* gv = (const uint2*)g_vn_pack;
    for (int z = t; z < HH; z += FWD_TB) cpk[z] = gc[z];
    for (int z = t; z < HH; z += FWD_TB) vpk[z] = gv[z];
    // channel tanh into sv (used only by first CN), T[0] into sw
    for (int n = t; n < NN; n += FWD_TB) {
        sv[n] = tanh_fast(0.5f * x[b * NN + n]);
        sw[n] = g_T[0][b][n];
    }
    if (t == 0) { sv[NN] = 0.0f; sv[HH] = 0.0f; }   // f-pad / CN-pad sentinels

    float bv_[NODES_PER_T];
    #pragma unroll
    for (int q = 0; q < NODES_PER_T; q++) bv_[q] = g_bval[t + FWD_TB * q];
    __syncthreads();

    // first CN: u = 2*atanh(clip(prod tanh(0.5 x) over M_first row))
    #pragma unroll
    for (int q = 0; q < NODES_PER_T; q++) {
        int i = t + FWD_TB * q;
        float prod = 1.0f; int nz = 0;
        #pragma unroll
        for (int k = 0; k < CAP_F; k++) {
            float v = sv[g_f_idx16[k * HH + i]];   // pad -> sv[NN]=0 -> skipped
            if (v != 0.0f) { prod *= v; nz++; }
        }
        su[i] = nz ? atanh2f(prod) : 0.0f;
    }
    __syncthreads();

    // 19 BP iterations, 2 syncs per layer
    for (int l = 0; l < NLAYER; l++) {
        // VN: v = tanh(0.5*(W u + bias))
        #pragma unroll
        for (int q = 0; q < NODES_PER_T; q++) {
            int i = t + FWD_TB * q;
            uint2 p = vpk[i];
            int j0 = p.x & 0xffff, j1 = p.x >> 16, j2 = p.y & 0xffff, jb = p.y >> 16;
            float acc = bv_[q] * sw[jb]
                      + g_vn_val[l][0][i] * su[j0]
                      + g_vn_val[l][1][i] * su[j1]
                      + g_vn_val[l][2][i] * su[j2];
            sv[i] = tanh_fast(0.5f * acc);
        }
        __syncthreads();

        // prefetch next bias row (CN never reads sw; VN done reading it)
        for (int n = t; n < NN; n += FWD_TB) sw[n] = g_T[l + 1][b][n];

        // CN fused with next atanh: u = 2*atanh(clip(prod v over M_cn row))
        #pragma unroll
        for (int q = 0; q < NODES_PER_T; q++) {
            int i = t + FWD_TB * q;
            uint4 cw = cpk[i];
            int j0 = cw.x & 0xffff, j1 = cw.x >> 16,
                j2 = cw.y & 0xffff, j3 = cw.y >> 16,
                j4 = cw.z & 0xffff, j5 = cw.z >> 16,
                j6 = cw.w & 0xffff;                     // slot 7 always pad
            float prod = 1.0f; int nz = 0;
            float v;
            v = sv[j0]; if (v != 0.0f) { prod *= v; nz++; }
            v = sv[j1]; if (v != 0.0f) { prod *= v; nz++; }
            v = sv[j2]; if (v != 0.0f) { prod *= v; nz++; }
            v = sv[j3]; if (v != 0.0f) { prod *= v; nz++; }
            v = sv[j4]; if (v != 0.0f) { prod *= v; nz++; }
            v = sv[j5]; if (v != 0.0f) { prod *= v; nz++; }
            v = sv[j6]; if (v != 0.0f) { prod *= v; nz++; }
            su[i] = nz ? atanh2f(prod) : 0.0f;
        }
        __syncthreads();
    }

    // output: sigmoid(u @ W_out.T + T[19] @ channel_mask); sw == T[19] already
    for (int n = t; n < NN; n += FWD_TB) {
        float acc = g_cmval[n] * sw[g_cmidx16[n]];
        #pragma unroll
        for (int k = 0; k < CAP_OUT; k++)
            acc += g_out_val[k * NN + n] * su[g_out_idx16[k * NN + n]]; // pad val=0
        out[b * NN + n] = 1.0f / (1.0f + __expf(-acc));
    }
}

// ---------------- launch ----------------
extern "C" void kernel_launch(void* const* d_in, const int* in_sizes, int n_in,
                              void* d_out, int out_size) {
    const float* x    = (const float*)d_in[0];   // [B,N]
    const float* Wvn  = (const float*)d_in[1];   // [19,H,H]
    const float* Wout = (const float*)d_in[2];   // [N,H]
    const float* S    = (const float*)d_in[3];   // [20,N,N]
    const float* bm   = (const float*)d_in[4];   // [N,H]
    const float* cm   = (const float*)d_in[5];   // [N,N]
    const float* Mf   = (const float*)d_in[6];   // [H,N]
    const float* Mcn  = (const float*)d_in[7];   // [H,H]
    float* out = (float*)d_out;

    const int TB = 256;

    // host-side attribute set (idempotent, cheap, outside capture semantics)
    cudaFuncSetAttribute(k_forward, cudaFuncAttributeMaxDynamicSharedMemorySize,
                         SM_TOTAL_BYTES);

    // 1) zero counters / defaults
    k_zero<<<(NSMAT * NN + TB - 1) / TB, TB>>>();

    // 2) merged vectorized scans
    int row_warps = 3 * HH + NN;                            // 9984
    k_scan_rows<<<(row_warps * 32 + TB - 1) / TB, TB>>>(Mf, Mcn, Wvn, Wout);
    k_scan_cols<<<2048, TB>>>(bm, cm, S);

    // 3) gather remaining W_vn layers at shared pattern (repacked [l][k][i])
    k_gather_w<<<((NLAYER - 1) * CAP_VN * HH + TB - 1) / TB, TB>>>(Wvn);

    // 4) precompute bias tensors T[l][b][n] = (llr @ S[l])
    k_compute_T<<<(NSMAT * BB * NN + TB - 1) / TB, TB>>>(x);

    // 5) fully fused forward pass: one block per batch element, state in smem
    k_forward<<<BB, FWD_TB, SM_TOTAL_BYTES>>>(x, out);
}

// round 7
// speedup vs baseline: 2.3622x; 1.1233x over previous
#include <cuda_runtime.h>
#include <math.h>
#include <stdint.h>

// Problem constants (fixed by the dataset)
#define BB 256
#define NN 768
#define HH 3072
#define NLAYER 19          // hidden VN/CN iterations
#define NSMAT 20           // S has 20 slices
#define CLIPV 0.999999f

// Sparsity capacities (actual: W_vn<=3, M_cn<=7, M_first<=7, W_out<=4, bm/cm/S col = 1)
#define CAP_VN 3
#define CAP_CN 7
#define CAP_F  7
#define CAP_OUT 4
#define CAP_S  4

// ---------------- device scratch (static; no allocation) ----------------
__device__ unsigned short g_f_idx16[CAP_F * HH];            // [k][i], pad -> NN
__device__ __align__(16) unsigned short g_cn_pack[HH * 8];  // [i][8], pad -> HH
__device__ __align__(8)  unsigned short g_vn_pack[HH * 4];  // [i][4]: j0,j1,j2,bias_idx
__device__ int            g_vn_cnt[HH];
__device__ float4         g_vn_val4[NLAYER][HH];            // (v0,v1,v2,0) per node
__device__ unsigned short g_out_idx16[CAP_OUT * NN];        // [k][n], pad -> 0 (val 0)
__device__ float          g_out_val  [CAP_OUT * NN];
__device__ float          g_bval  [HH];
__device__ unsigned short g_cmidx16[NN];
__device__ float          g_cmval  [NN];

__device__ int   g_s_idx[NSMAT * NN * CAP_S];
__device__ int   g_s_cnt[NSMAT * NN];
__device__ float g_s_val[NSMAT * NN * CAP_S];

__device__ float g_T[NSMAT][BB][NN];   // T[l][b][n] = (llr @ S[l])[b][n]

// ---------------- helpers ----------------
__device__ __forceinline__ float atanh2f(float x) {
    // 2*atanh(clip(x)) = ln2*(log2(1+x) - log2(1-x))
    x = fminf(fmaxf(x, -CLIPV), CLIPV);
    return 0.69314718055994531f * (__log2f(1.0f + x) - __log2f(1.0f - x));
}
__device__ __forceinline__ float tanh_fast(float y) {
    // stable for all y: exp overflow -> inf -> result +/-1
    return 1.0f - 2.0f / (1.0f + __expf(2.0f * y));
}

// pipelined float4 row scan: independent ballots + prefetch; emit(pos,col,val)
template <class F>
__device__ __forceinline__ int scan_row_f4(const float* __restrict__ row,
                                           int cols, int lane, F emit) {
    const float4* r4 = reinterpret_cast<const float4*>(row);
    const int nIter = cols / 128;           // 128 floats per warp-iteration
    unsigned below = (1u << lane) - 1u;
    int c = 0;
    float4 v = r4[lane];
    for (int it = 0; it < nIter; it++) {
        float4 vn = v;
        if (it + 1 < nIter) vn = r4[(it + 1) * 32 + lane];
        unsigned m0 = __ballot_sync(0xffffffffu, v.x != 0.0f);
        unsigned m1 = __ballot_sync(0xffffffffu, v.y != 0.0f);
        unsigned m2 = __ballot_sync(0xffffffffu, v.z != 0.0f);
        unsigned m3 = __ballot_sync(0xffffffffu, v.w != 0.0f);
        int c0 = c;
        int c1 = c0 + __popc(m0);
        int c2 = c1 + __popc(m1);
        int c3 = c2 + __popc(m2);
        int col0 = (it * 32 + lane) * 4;
        if (v.x != 0.0f) emit(c0 + __popc(m0 & below), col0 + 0, v.x);
        if (v.y != 0.0f) emit(c1 + __popc(m1 & below), col0 + 1, v.y);
        if (v.z != 0.0f) emit(c2 + __popc(m2 & below), col0 + 2, v.z);
        if (v.w != 0.0f) emit(c3 + __popc(m3 & below), col0 + 3, v.w);
        c = c3 + __popc(m3);
        v = vn;
    }
    return c;
}

// ---------------- setup kernels ----------------
__global__ void k_zero() {
    int t = blockIdx.x * blockDim.x + threadIdx.x;
    if (t < HH)         { g_bval[t] = 0.0f; g_vn_pack[t * 4 + 3] = 0; }
    if (t < NN)         { g_cmidx16[t] = 0; g_cmval[t] = 0.0f; }
    if (t < NSMAT * NN) g_s_cnt[t] = 0;
}

// merged row scans: Mf | Mcn | Wvn layer0 | Wout, one warp per row
__global__ void k_scan_rows(const float* __restrict__ Mf,
                            const float* __restrict__ Mcn,
                            const float* __restrict__ Wvn,
                            const float* __restrict__ Wout) {
    int gw = (blockIdx.x * blockDim.x + threadIdx.x) >> 5;
    int lane = threadIdx.x & 31;

    if (gw < HH) {                                    // Mf [HH x NN]
        int w = gw;
        int c = scan_row_f4(Mf + (size_t)w * NN, NN, lane,
            [&](int p, int col, float) { if (p < CAP_F) g_f_idx16[p * HH + w] = (unsigned short)col; });
        if (c > CAP_F) c = CAP_F;
        if (lane >= c && lane < CAP_F) g_f_idx16[lane * HH + w] = (unsigned short)NN;
    } else if (gw < 2 * HH) {                         // Mcn [HH x HH]
        int w = gw - HH;
        int c = scan_row_f4(Mcn + (size_t)w * HH, HH, lane,
            [&](int p, int col, float) { if (p < CAP_CN) g_cn_pack[w * 8 + p] = (unsigned short)col; });
        if (c > CAP_CN) c = CAP_CN;
        if (lane >= c && lane < 8) g_cn_pack[w * 8 + lane] = (unsigned short)HH;
    } else if (gw < 3 * HH) {                         // Wvn layer 0 [HH x HH]
        int w = gw - 2 * HH;
        float* vb = (float*)&g_vn_val4[0][0];
        int c = scan_row_f4(Wvn + (size_t)w * HH, HH, lane,
            [&](int p, int col, float v) {
                if (p < CAP_VN) { g_vn_pack[w * 4 + p] = (unsigned short)col; vb[w * 4 + p] = v; } });
        if (c > CAP_VN) c = CAP_VN;
        if (lane >= c && lane < CAP_VN) g_vn_pack[w * 4 + lane] = 0;   // slot 3 = bias idx, untouched
        if (lane >= c && lane < 4)      vb[w * 4 + lane] = 0.0f;       // zero val pads + w comp
        if (lane == 0) g_vn_cnt[w] = c;
    } else if (gw < 3 * HH + NN) {                    // Wout [NN x HH]
        int w = gw - 3 * HH;
        int c = scan_row_f4(Wout + (size_t)w * HH, HH, lane,
            [&](int p, int col, float v) {
                if (p < CAP_OUT) { g_out_idx16[p * NN + w] = (unsigned short)col; g_out_val[p * NN + w] = v; } });
        if (c > CAP_OUT) c = CAP_OUT;
        if (lane >= c && lane < CAP_OUT) { g_out_idx16[lane * NN + w] = 0; g_out_val[lane * NN + w] = 0.0f; }
    }
}

// merged column scans: bm (1 nz/col), cm (1 nz/col), S (atomic append)
__global__ void k_scan_cols(const float* __restrict__ bm,
                            const float* __restrict__ cm,
                            const float* __restrict__ S) {
    int tid = blockIdx.x * blockDim.x + threadIdx.x;
    int stride = gridDim.x * blockDim.x;

    const float4* b4 = reinterpret_cast<const float4*>(bm);
    for (int t = tid; t < NN * HH / 4; t += stride) {
        float4 v = b4[t];
        float a[4] = {v.x, v.y, v.z, v.w};
        #pragma unroll
        for (int s = 0; s < 4; s++) if (a[s] != 0.0f) {
            int f = t * 4 + s, col = f % HH, row = f / HH;
            g_bval[col] = a[s];
            g_vn_pack[col * 4 + 3] = (unsigned short)row;   // bias idx in slot 3
        }
    }
    const float4* c4 = reinterpret_cast<const float4*>(cm);
    for (int t = tid; t < NN * NN / 4; t += stride) {
        float4 v = c4[t];
        float a[4] = {v.x, v.y, v.z, v.w};
        #pragma unroll
        for (int s = 0; s < 4; s++) if (a[s] != 0.0f) {
            int f = t * 4 + s, col = f % NN, row = f / NN;
            g_cmval[col] = a[s];
            g_cmidx16[col] = (unsigned short)row;
        }
    }
    const float4* s4 = reinterpret_cast<const float4*>(S);
    for (int t = tid; t < NSMAT * NN * NN / 4; t += stride) {
        float4 v = s4[t];
        float a[4] = {v.x, v.y, v.z, v.w};
        #pragma unroll
        for (int s = 0; s < 4; s++) if (a[s] != 0.0f) {
            int f = t * 4 + s;
            int c = f % NN, r = (f / NN) % NN, l = f / (NN * NN);
            int colI = l * NN + c;
            int pos = atomicAdd(&g_s_cnt[colI], 1);
            if (pos < CAP_S) { g_s_idx[colI * CAP_S + pos] = r; g_s_val[colI * CAP_S + pos] = a[s]; }
        }
    }
}

// gather W_vn for layers 1..18: thread = (layer, node), 3 parallel loads + STG.128
__global__ void k_gather_w(const float* __restrict__ W) {
    int t = blockIdx.x * blockDim.x + threadIdx.x;
    if (t >= (NLAYER - 1) * HH) return;
    int l = t / HH + 1;
    int i = t % HH;
    int c = g_vn_cnt[i];
    const float* Wl = W + (size_t)l * HH * HH + (size_t)i * HH;
    float4 o = make_float4(0.0f, 0.0f, 0.0f, 0.0f);
    if (c > 0) o.x = Wl[g_vn_pack[i * 4 + 0]];
    if (c > 1) o.y = Wl[g_vn_pack[i * 4 + 1]];
    if (c > 2) o.z = Wl[g_vn_pack[i * 4 + 2]];
    g_vn_val4[l][i] = o;
}

// T[l][b][n] = sum_m x[b][m] * S[l][m][n]
__global__ void k_compute_T(const float* __restrict__ x) {
    int t = blockIdx.x * blockDim.x + threadIdx.x;
    if (t >= NSMAT * BB * NN) return;
    int n = t % NN;
    int b = (t / NN) % BB;
    int l = t / (BB * NN);
    int ln = l * NN + n;
    int c = g_s_cnt[ln]; if (c > CAP_S) c = CAP_S;
    float acc = 0.0f;
    for (int k = 0; k < c; k++)
        acc += g_s_val[ln * CAP_S + k] * x[b * NN + g_s_idx[ln * CAP_S + k]];
    g_T[l][b][n] = acc;
}

// ---------------- fused forward: one block per PAIR of batch elements ----------------
#define FWD_TB 1024
#define NODES_PER_T (HH / FWD_TB)   // 3

// smem: uint4 cpk[HH] | uint2 vpk[HH] | float2 su2[HH] | float2 sv2[HH+1] | float2 sw2[NN]
#define SM_TOTAL_BYTES (HH * 16 + HH * 8 + HH * 8 + (HH + 1) * 8 + NN * 8)  // 129032

__global__ void __launch_bounds__(FWD_TB)
k_forward(const float* __restrict__ x, float* __restrict__ out) {
    extern __shared__ char smem[];
    uint4*  cpk = (uint4*)smem;                // [HH] packed CN idx (8 u16)
    uint2*  vpk = (uint2*)(cpk + HH);          // [HH] packed VN idx (3 u16 + bias idx)
    float2* su2 = (float2*)(vpk + HH);         // [HH]     state u, both batches
    float2* sv2 = su2 + HH;                    // [HH+1]   state v, sv2[HH]=0 sentinel
    float2* sw2 = sv2 + HH + 1;                // [NN]     bias row, both batches

    const int b0 = blockIdx.x * 2;
    const int b1 = b0 + 1;
    const int t = threadIdx.x;

    // stage packed indices (vectorized, L2-broadcast)
    const uint4* gc = (const uint4*)g_cn_pack;
    const uint2* gv = (const uint2*)g_vn_pack;
    for (int z = t; z < HH; z += FWD_TB) { cpk[z] = gc[z]; vpk[z] = gv[z]; }
    // channel tanh into sv2 (first CN input), T[0] into sw2
    for (int n = t; n < NN; n += FWD_TB) {
        sv2[n] = make_float2(tanh_fast(0.5f * x[b0 * NN + n]),
                             tanh_fast(0.5f * x[b1 * NN + n]));
        sw2[n] = make_float2(g_T[0][b0][n], g_T[0][b1][n]);
    }
    if (t == NN)  sv2[NN] = make_float2(0.0f, 0.0f);   // first-CN pad sentinel
    if (t == 0)   sv2[HH] = make_float2(0.0f, 0.0f);   // CN pad sentinel

    float bv_[NODES_PER_T];
    #pragma unroll
    for (int q = 0; q < NODES_PER_T; q++) bv_[q] = g_bval[t + FWD_TB * q];
    __syncthreads();

    // first CN: u = 2*atanh(clip(prod tanh(0.5 x) over M_first row))
    #pragma unroll
    for (int q = 0; q < NODES_PER_T; q++) {
        int i = t + FWD_TB * q;
        float p0 = 1.0f, p1 = 1.0f; int n0 = 0, n1 = 0;
        #pragma unroll
        for (int k = 0; k < CAP_F; k++) {
            float2 vv = sv2[g_f_idx16[k * HH + i]];    // pad -> sv2[NN]=0 -> skipped
            if (vv.x != 0.0f) { p0 *= vv.x; n0++; }
            if (vv.y != 0.0f) { p1 *= vv.y; n1++; }
        }
        su2[i] = make_float2(n0 ? atanh2f(p0) : 0.0f, n1 ? atanh2f(p1) : 0.0f);
    }
    __syncthreads();

    // 19 BP iterations, 2 syncs per layer
    for (int l = 0; l < NLAYER; l++) {
        // VN: v = tanh(0.5*(W u + bias))
        #pragma unroll
        for (int q = 0; q < NODES_PER_T; q++) {
            int i = t + FWD_TB * q;
            uint2 p = vpk[i];
            int j0 = p.x & 0xffff, j1 = p.x >> 16, j2 = p.y & 0xffff, jb = p.y >> 16;
            float4 w4 = g_vn_val4[l][i];               // LDG.128, L2/L1 resident
            float2 u0 = su2[j0], u1 = su2[j1], u2 = su2[j2], tb = sw2[jb];
            float a0 = bv_[q] * tb.x + w4.x * u0.x + w4.y * u1.x + w4.z * u2.x;
            float a1 = bv_[q] * tb.y + w4.x * u0.y + w4.y * u1.y + w4.z * u2.y;
            sv2[i] = make_float2(tanh_fast(0.5f * a0), tanh_fast(0.5f * a1));
        }
        __syncthreads();

        // prefetch next bias row (CN never reads sw2; VN done reading it)
        for (int n = t; n < NN; n += FWD_TB)
            sw2[n] = make_float2(g_T[l + 1][b0][n], g_T[l + 1][b1][n]);

        // CN fused with next atanh: u = 2*atanh(clip(prod v over M_cn row))
        #pragma unroll
        for (int q = 0; q < NODES_PER_T; q++) {
            int i = t + FWD_TB * q;
            uint4 cw = cpk[i];
            int j0 = cw.x & 0xffff, j1 = cw.x >> 16,
                j2 = cw.y & 0xffff, j3 = cw.y >> 16,
                j4 = cw.z & 0xffff, j5 = cw.z >> 16,
                j6 = cw.w & 0xffff;                     // slot 7 always pad
            float p0 = 1.0f, p1 = 1.0f; int n0 = 0, n1 = 0;
            float2 vv;
            vv = sv2[j0]; if (vv.x != 0.0f) { p0 *= vv.x; n0++; } if (vv.y != 0.0f) { p1 *= vv.y; n1++; }
            vv = sv2[j1]; if (vv.x != 0.0f) { p0 *= vv.x; n0++; } if (vv.y != 0.0f) { p1 *= vv.y; n1++; }
            vv = sv2[j2]; if (vv.x != 0.0f) { p0 *= vv.x; n0++; } if (vv.y != 0.0f) { p1 *= vv.y; n1++; }
            vv = sv2[j3]; if (vv.x != 0.0f) { p0 *= vv.x; n0++; } if (vv.y != 0.0f) { p1 *= vv.y; n1++; }
            vv = sv2[j4]; if (vv.x != 0.0f) { p0 *= vv.x; n0++; } if (vv.y != 0.0f) { p1 *= vv.y; n1++; }
            vv = sv2[j5]; if (vv.x != 0.0f) { p0 *= vv.x; n0++; } if (vv.y != 0.0f) { p1 *= vv.y; n1++; }
            vv = sv2[j6]; if (vv.x != 0.0f) { p0 *= vv.x; n0++; } if (vv.y != 0.0f) { p1 *= vv.y; n1++; }
            su2[i] = make_float2(n0 ? atanh2f(p0) : 0.0f, n1 ? atanh2f(p1) : 0.0f);
        }
        __syncthreads();
    }

    // output: sigmoid(u @ W_out.T + T[19] @ channel_mask); sw2 == T[19] already
    for (int n = t; n < NN; n += FWD_TB) {
        float2 tb = sw2[g_cmidx16[n]];
        float a0 = g_cmval[n] * tb.x;
        float a1 = g_cmval[n] * tb.y;
        #pragma unroll
        for (int k = 0; k < CAP_OUT; k++) {
            float2 uu = su2[g_out_idx16[k * NN + n]];  // pad val=0
            float wv = g_out_val[k * NN + n];
            a0 += wv * uu.x;
            a1 += wv * uu.y;
        }
        out[b0 * NN + n] = 1.0f / (1.0f + __expf(-a0));
        out[b1 * NN + n] = 1.0f / (1.0f + __expf(-a1));
    }
}

// ---------------- launch ----------------
extern "C" void kernel_launch(void* const* d_in, const int* in_sizes, int n_in,
                              void* d_out, int out_size) {
    const float* x    = (const float*)d_in[0];   // [B,N]
    const float* Wvn  = (const float*)d_in[1];   // [19,H,H]
    const float* Wout = (const float*)d_in[2];   // [N,H]
    const float* S    = (const float*)d_in[3];   // [20,N,N]
    const float* bm   = (const float*)d_in[4];   // [N,H]
    const float* cm   = (const float*)d_in[5];   // [N,N]
    const float* Mf   = (const float*)d_in[6];   // [H,N]
    const float* Mcn  = (const float*)d_in[7];   // [H,H]
    float* out = (float*)d_out;

    const int TB = 256;

    // host-side attribute set (idempotent, cheap, outside capture semantics)
    cudaFuncSetAttribute(k_forward, cudaFuncAttributeMaxDynamicSharedMemorySize,
                         SM_TOTAL_BYTES);

    // 1) zero counters / defaults
    k_zero<<<(NSMAT * NN + TB - 1) / TB, TB>>>();

    // 2) merged vectorized scans (pipelined independent-ballot version)
    int row_warps = 3 * HH + NN;                            // 9984
    k_scan_rows<<<(row_warps * 32 + 511) / 512, 512>>>(Mf, Mcn, Wvn, Wout);
    k_scan_cols<<<2048, TB>>>(bm, cm, S);

    // 3) gather remaining W_vn layers at shared pattern (float4 [l][i])
    k_gather_w<<<((NLAYER - 1) * HH + TB - 1) / TB, TB>>>(Wvn);

    // 4) precompute bias tensors T[l][b][n] = (llr @ S[l])
    k_compute_T<<<(NSMAT * BB * NN + TB - 1) / TB, TB>>>(x);

    // 5) fused forward: one block per batch PAIR, float2 state in smem
    k_forward<<<BB / 2, FWD_TB, SM_TOTAL_BYTES>>>(x, out);
}

// round 8
// speedup vs baseline: 2.6350x; 1.1155x over previous
#include <cuda_runtime.h>
#include <math.h>
#include <stdint.h>

// Problem constants (fixed by the dataset)
#define BB 256
#define NN 768
#define HH 3072
#define NLAYER 19          // hidden VN/CN iterations
#define NSMAT 20           // S has 20 slices
#define CLIPV 0.999999f

// Sparsity capacities (actual: W_vn<=3, M_cn<=7, M_first<=7, W_out<=4, bm/cm/S col = 1)
#define CAP_VN 3
#define CAP_CN 7
#define CAP_F  7
#define CAP_OUT 4
#define CAP_S  4

// ---------------- device scratch (static; no allocation) ----------------
__device__ unsigned short g_f_idx16[CAP_F * HH];            // [k][i], pad -> NN
__device__ __align__(16) unsigned short g_cn_pack[HH * 8];  // [i][8], pad -> HH
__device__ __align__(8)  unsigned short g_vn_pack[HH * 4];  // [i][4]: j0,j1,j2,bias_idx
__device__ int            g_vn_cnt[HH];
__device__ float4         g_vn_val4[NLAYER][HH];            // (v0,v1,v2,-) per node
__device__ unsigned short g_out_idx16[CAP_OUT * NN];        // [k][n], pad -> 0 (val 0)
__device__ float          g_out_val  [CAP_OUT * NN];
__device__ float          g_bval  [HH];
__device__ unsigned short g_cmidx16[NN];
__device__ float          g_cmval  [NN];

__device__ int   g_s_idx[NSMAT * NN * CAP_S];
__device__ int   g_s_cnt[NSMAT * NN];
__device__ float g_s_val[NSMAT * NN * CAP_S];

// ---------------- helpers ----------------
__device__ __forceinline__ float atanh2f(float x) {
    // 2*atanh(clip(x)) = ln2*(log2(1+x) - log2(1-x))
    x = fminf(fmaxf(x, -CLIPV), CLIPV);
    return 0.69314718055994531f * (__log2f(1.0f + x) - __log2f(1.0f - x));
}
__device__ __forceinline__ float tanh_fast(float y) {
    // stable for all y: exp overflow -> inf -> __fdividef(2,inf)=0 -> result 1
    return 1.0f - __fdividef(2.0f, 1.0f + __expf(2.0f * y));
}

// pipelined float4 row scan: independent ballots + prefetch; emit(pos,col,val)
template <class F>
__device__ __forceinline__ int scan_row_f4(const float* __restrict__ row,
                                           int cols, int lane, F emit) {
    const float4* r4 = reinterpret_cast<const float4*>(row);
    const int nIter = cols / 128;           // 128 floats per warp-iteration
    unsigned below = (1u << lane) - 1u;
    int c = 0;
    float4 v = r4[lane];
    for (int it = 0; it < nIter; it++) {
        float4 vn = v;
        if (it + 1 < nIter) vn = r4[(it + 1) * 32 + lane];
        unsigned m0 = __ballot_sync(0xffffffffu, v.x != 0.0f);
        unsigned m1 = __ballot_sync(0xffffffffu, v.y != 0.0f);
        unsigned m2 = __ballot_sync(0xffffffffu, v.z != 0.0f);
        unsigned m3 = __ballot_sync(0xffffffffu, v.w != 0.0f);
        int c0 = c;
        int c1 = c0 + __popc(m0);
        int c2 = c1 + __popc(m1);
        int c3 = c2 + __popc(m2);
        int col0 = (it * 32 + lane) * 4;
        if (v.x != 0.0f) emit(c0 + __popc(m0 & below), col0 + 0, v.x);
        if (v.y != 0.0f) emit(c1 + __popc(m1 & below), col0 + 1, v.y);
        if (v.z != 0.0f) emit(c2 + __popc(m2 & below), col0 + 2, v.z);
        if (v.w != 0.0f) emit(c3 + __popc(m3 & below), col0 + 3, v.w);
        c = c3 + __popc(m3);
        v = vn;
    }
    return c;
}

// ---------------- setup kernels ----------------
__global__ void k_zero() {
    int t = blockIdx.x * blockDim.x + threadIdx.x;
    if (t < HH)         { g_bval[t] = 0.0f; g_vn_pack[t * 4 + 3] = 0; }
    if (t < NN)         { g_cmidx16[t] = 0; g_cmval[t] = 0.0f; }
    if (t < NSMAT * NN) g_s_cnt[t] = 0;
}

// merged row scans: Mf | Mcn | Wvn layer0 | Wout, one warp per row
__global__ void k_scan_rows(const float* __restrict__ Mf,
                            const float* __restrict__ Mcn,
                            const float* __restrict__ Wvn,
                            const float* __restrict__ Wout) {
    int gw = (blockIdx.x * blockDim.x + threadIdx.x) >> 5;
    int lane = threadIdx.x & 31;

    if (gw < HH) {                                    // Mf [HH x NN]
        int w = gw;
        int c = scan_row_f4(Mf + (size_t)w * NN, NN, lane,
            [&](int p, int col, float) { if (p < CAP_F) g_f_idx16[p * HH + w] = (unsigned short)col; });
        if (c > CAP_F) c = CAP_F;
        if (lane >= c && lane < CAP_F) g_f_idx16[lane * HH + w] = (unsigned short)NN;
    } else if (gw < 2 * HH) {                         // Mcn [HH x HH]
        int w = gw - HH;
        int c = scan_row_f4(Mcn + (size_t)w * HH, HH, lane,
            [&](int p, int col, float) { if (p < CAP_CN) g_cn_pack[w * 8 + p] = (unsigned short)col; });
        if (c > CAP_CN) c = CAP_CN;
        if (lane >= c && lane < 8) g_cn_pack[w * 8 + lane] = (unsigned short)HH;
    } else if (gw < 3 * HH) {                         // Wvn layer 0 [HH x HH]
        int w = gw - 2 * HH;
        float* vb = (float*)&g_vn_val4[0][0];
        int c = scan_row_f4(Wvn + (size_t)w * HH, HH, lane,
            [&](int p, int col, float v) {
                if (p < CAP_VN) { g_vn_pack[w * 4 + p] = (unsigned short)col; vb[w * 4 + p] = v; } });
        if (c > CAP_VN) c = CAP_VN;
        if (lane >= c && lane < CAP_VN) g_vn_pack[w * 4 + lane] = 0;   // slot 3 = bias idx, untouched
        if (lane >= c && lane < 4)      vb[w * 4 + lane] = 0.0f;       // zero val pads + w comp
        if (lane == 0) g_vn_cnt[w] = c;
    } else if (gw < 3 * HH + NN) {                    // Wout [NN x HH]
        int w = gw - 3 * HH;
        int c = scan_row_f4(Wout + (size_t)w * HH, HH, lane,
            [&](int p, int col, float v) {
                if (p < CAP_OUT) { g_out_idx16[p * NN + w] = (unsigned short)col; g_out_val[p * NN + w] = v; } });
        if (c > CAP_OUT) c = CAP_OUT;
        if (lane >= c && lane < CAP_OUT) { g_out_idx16[lane * NN + w] = 0; g_out_val[lane * NN + w] = 0.0f; }
    }
}

// merged column scans: bm (1 nz/col), cm (1 nz/col), S (atomic append)
__global__ void k_scan_cols(const float* __restrict__ bm,
                            const float* __restrict__ cm,
                            const float* __restrict__ S) {
    int tid = blockIdx.x * blockDim.x + threadIdx.x;
    int stride = gridDim.x * blockDim.x;

    const float4* b4 = reinterpret_cast<const float4*>(bm);
    for (int t = tid; t < NN * HH / 4; t += stride) {
        float4 v = b4[t];
        float a[4] = {v.x, v.y, v.z, v.w};
        #pragma unroll
        for (int s = 0; s < 4; s++) if (a[s] != 0.0f) {
            int f = t * 4 + s, col = f % HH, row = f / HH;
            g_bval[col] = a[s];
            g_vn_pack[col * 4 + 3] = (unsigned short)row;   // bias idx in slot 3
        }
    }
    const float4* c4 = reinterpret_cast<const float4*>(cm);
    for (int t = tid; t < NN * NN / 4; t += stride) {
        float4 v = c4[t];
        float a[4] = {v.x, v.y, v.z, v.w};
        #pragma unroll
        for (int s = 0; s < 4; s++) if (a[s] != 0.0f) {
            int f = t * 4 + s, col = f % NN, row = f / NN;
            g_cmval[col] = a[s];
            g_cmidx16[col] = (unsigned short)row;
        }
    }
    const float4* s4 = reinterpret_cast<const float4*>(S);
    for (int t = tid; t < NSMAT * NN * NN / 4; t += stride) {
        float4 v = s4[t];
        float a[4] = {v.x, v.y, v.z, v.w};
        #pragma unroll
        for (int s = 0; s < 4; s++) if (a[s] != 0.0f) {
            int f = t * 4 + s;
            int c = f % NN, r = (f / NN) % NN, l = f / (NN * NN);
            int colI = l * NN + c;
            int pos = atomicAdd(&g_s_cnt[colI], 1);
            if (pos < CAP_S) { g_s_idx[colI * CAP_S + pos] = r; g_s_val[colI * CAP_S + pos] = a[s]; }
        }
    }
}

// gather W_vn for layers 1..18: thread = (layer, k, node) — max parallelism/MLP
__global__ void k_gather_w(const float* __restrict__ W) {
    int t = blockIdx.x * blockDim.x + threadIdx.x;
    if (t >= (NLAYER - 1) * CAP_VN * HH) return;
    int i = t % HH;
    int r = t / HH;
    int k = r % CAP_VN;
    int l = r / CAP_VN + 1;
    float v = 0.0f;
    if (k < g_vn_cnt[i])
        v = W[(size_t)l * HH * HH + (size_t)i * HH + g_vn_pack[i * 4 + k]];
    ((float*)&g_vn_val4[l][i])[k] = v;
}

// ---------------- fused forward: one block per PAIR of batch elements ----------------
#define FWD_TB 1024
#define NODES_PER_T (HH / FWD_TB)   // 3

// smem: uint4 cpk[HH] | uint2 vpk[HH] | float2 su2[HH] | float2 sv2[HH+1] | float2 sw2[NN] | float2 sx2[NN]
#define SM_TOTAL_BYTES (HH * 16 + HH * 8 + HH * 8 + (HH + 1) * 8 + NN * 8 + NN * 8)  // 135176

__global__ void __launch_bounds__(FWD_TB)
k_forward(const float* __restrict__ x, float* __restrict__ out) {
    extern __shared__ char smem[];
    uint4*  cpk = (uint4*)smem;                // [HH] packed CN idx (8 u16)
    uint2*  vpk = (uint2*)(cpk + HH);          // [HH] packed VN idx (3 u16 + bias idx)
    float2* su2 = (float2*)(vpk + HH);         // [HH]     state u, both batches
    float2* sv2 = su2 + HH;                    // [HH+1]   state v, sv2[HH]=0 sentinel
    float2* sw2 = sv2 + HH + 1;                // [NN]     bias row, both batches
    float2* sx2 = sw2 + NN;                    // [NN]     channel LLR rows

    const int b0 = blockIdx.x * 2;
    const int b1 = b0 + 1;
    const int t = threadIdx.x;

    // stage packed indices (vectorized, L2-broadcast)
    const uint4* gc = (const uint4*)g_cn_pack;
    const uint2* gv = (const uint2*)g_vn_pack;
    for (int z = t; z < HH; z += FWD_TB) { cpk[z] = gc[z]; vpk[z] = gv[z]; }
    // x rows + channel tanh into sv2 (first CN input)
    for (int n = t; n < NN; n += FWD_TB) {
        float x0 = x[b0 * NN + n], x1 = x[b1 * NN + n];
        sx2[n] = make_float2(x0, x1);
        sv2[n] = make_float2(tanh_fast(0.5f * x0), tanh_fast(0.5f * x1));
    }
    if (t == NN)  sv2[NN] = make_float2(0.0f, 0.0f);   // first-CN pad sentinel
    if (t == 0)   sv2[HH] = make_float2(0.0f, 0.0f);   // CN pad sentinel

    float bv_[NODES_PER_T];
    #pragma unroll
    for (int q = 0; q < NODES_PER_T; q++) bv_[q] = g_bval[t + FWD_TB * q];
    __syncthreads();

    // bias row for layer 0: T[0][b][n] = sum_m x[b][m]*S[0][m][n] (sparse, ~1 nz)
    for (int n = t; n < NN; n += FWD_TB) {
        int ln = n;                                    // l=0
        int c = g_s_cnt[ln]; if (c > CAP_S) c = CAP_S;
        float a0 = 0.0f, a1 = 0.0f;
        for (int k = 0; k < c; k++) {
            float sv_ = g_s_val[ln * CAP_S + k];
            float2 xx = sx2[g_s_idx[ln * CAP_S + k]];
            a0 += sv_ * xx.x; a1 += sv_ * xx.y;
        }
        sw2[n] = make_float2(a0, a1);
    }

    // first CN: u = 2*atanh(clip(prod tanh(0.5 x) over M_first row))
    #pragma unroll
    for (int q = 0; q < NODES_PER_T; q++) {
        int i = t + FWD_TB * q;
        float p0 = 1.0f, p1 = 1.0f; int n0 = 0, n1 = 0;
        #pragma unroll
        for (int k = 0; k < CAP_F; k++) {
            float2 vv = sv2[g_f_idx16[k * HH + i]];    // pad -> sv2[NN]=0 -> skipped
            if (vv.x != 0.0f) { p0 *= vv.x; n0++; }
            if (vv.y != 0.0f) { p1 *= vv.y; n1++; }
        }
        su2[i] = make_float2(n0 ? atanh2f(p0) : 0.0f, n1 ? atanh2f(p1) : 0.0f);
    }
    __syncthreads();

    // 19 BP iterations, 2 syncs per layer
    for (int l = 0; l < NLAYER; l++) {
        // VN: v = tanh(0.5*(W u + bias))
        #pragma unroll
        for (int q = 0; q < NODES_PER_T; q++) {
            int i = t + FWD_TB * q;
            uint2 p = vpk[i];
            int j0 = p.x & 0xffff, j1 = p.x >> 16, j2 = p.y & 0xffff, jb = p.y >> 16;
            float4 w4 = g_vn_val4[l][i];               // LDG.128, L2/L1 resident
            float2 u0 = su2[j0], u1 = su2[j1], u2 = su2[j2], tb = sw2[jb];
            float a0 = bv_[q] * tb.x + w4.x * u0.x + w4.y * u1.x + w4.z * u2.x;
            float a1 = bv_[q] * tb.y + w4.x * u0.y + w4.y * u1.y + w4.z * u2.y;
            sv2[i] = make_float2(tanh_fast(0.5f * a0), tanh_fast(0.5f * a1));
        }
        __syncthreads();

        // compute next layer's bias row (CN never reads sw2; VN done reading it)
        for (int n = t; n < NN; n += FWD_TB) {
            int ln = (l + 1) * NN + n;
            int c = g_s_cnt[ln]; if (c > CAP_S) c = CAP_S;
            float a0 = 0.0f, a1 = 0.0f;
            for (int k = 0; k < c; k++) {
                float sv_ = g_s_val[ln * CAP_S + k];
                float2 xx = sx2[g_s_idx[ln * CAP_S + k]];
                a0 += sv_ * xx.x; a1 += sv_ * xx.y;
            }
            sw2[n] = make_float2(a0, a1);
        }

        // CN fused with next atanh: u = 2*atanh(clip(prod v over M_cn row))
        #pragma unroll
        for (int q = 0; q < NODES_PER_T; q++) {
            int i = t + FWD_TB * q;
            uint4 cw = cpk[i];
            int j0 = cw.x & 0xffff, j1 = cw.x >> 16,
                j2 = cw.y & 0xffff, j3 = cw.y >> 16,
                j4 = cw.z & 0xffff, j5 = cw.z >> 16,
                j6 = cw.w & 0xffff;                     // slot 7 always pad
            float p0 = 1.0f, p1 = 1.0f; int n0 = 0, n1 = 0;
            float2 vv;
            vv = sv2[j0]; if (vv.x != 0.0f) { p0 *= vv.x; n0++; } if (vv.y != 0.0f) { p1 *= vv.y; n1++; }
            vv = sv2[j1]; if (vv.x != 0.0f) { p0 *= vv.x; n0++; } if (vv.y != 0.0f) { p1 *= vv.y; n1++; }
            vv = sv2[j2]; if (vv.x != 0.0f) { p0 *= vv.x; n0++; } if (vv.y != 0.0f) { p1 *= vv.y; n1++; }
            vv = sv2[j3]; if (vv.x != 0.0f) { p0 *= vv.x; n0++; } if (vv.y != 0.0f) { p1 *= vv.y; n1++; }
            vv = sv2[j4]; if (vv.x != 0.0f) { p0 *= vv.x; n0++; } if (vv.y != 0.0f) { p1 *= vv.y; n1++; }
            vv = sv2[j5]; if (vv.x != 0.0f) { p0 *= vv.x; n0++; } if (vv.y != 0.0f) { p1 *= vv.y; n1++; }
            vv = sv2[j6]; if (vv.x != 0.0f) { p0 *= vv.x; n0++; } if (vv.y != 0.0f) { p1 *= vv.y; n1++; }
            su2[i] = make_float2(n0 ? atanh2f(p0) : 0.0f, n1 ? atanh2f(p1) : 0.0f);
        }
        __syncthreads();
    }

    // output: sigmoid(u @ W_out.T + T[19] @ channel_mask); sw2 == T[19] already
    for (int n = t; n < NN; n += FWD_TB) {
        float2 tb = sw2[g_cmidx16[n]];
        float a0 = g_cmval[n] * tb.x;
        float a1 = g_cmval[n] * tb.y;
        #pragma unroll
        for (int k = 0; k < CAP_OUT; k++) {
            float2 uu = su2[g_out_idx16[k * NN + n]];  // pad val=0
            float wv = g_out_val[k * NN + n];
            a0 += wv * uu.x;
            a1 += wv * uu.y;
        }
        out[b0 * NN + n] = __fdividef(1.0f, 1.0f + __expf(-a0));
        out[b1 * NN + n] = __fdividef(1.0f, 1.0f + __expf(-a1));
    }
}

// ---------------- launch ----------------
extern "C" void kernel_launch(void* const* d_in, const int* in_sizes, int n_in,
                              void* d_out, int out_size) {
    const float* x    = (const float*)d_in[0];   // [B,N]
    const float* Wvn  = (const float*)d_in[1];   // [19,H,H]
    const float* Wout = (const float*)d_in[2];   // [N,H]
    const float* S    = (const float*)d_in[3];   // [20,N,N]
    const float* bm   = (const float*)d_in[4];   // [N,H]
    const float* cm   = (const float*)d_in[5];   // [N,N]
    const float* Mf   = (const float*)d_in[6];   // [H,N]
    const float* Mcn  = (const float*)d_in[7];   // [H,H]
    float* out = (float*)d_out;

    const int TB = 256;

    // host-side attribute set (idempotent, cheap, outside capture semantics)
    cudaFuncSetAttribute(k_forward, cudaFuncAttributeMaxDynamicSharedMemorySize,
                         SM_TOTAL_BYTES);

    // 1) zero counters / defaults
    k_zero<<<(NSMAT * NN + TB - 1) / TB, TB>>>();

    // 2) merged vectorized scans (pipelined independent-ballot version)
    int row_warps = 3 * HH + NN;                            // 9984
    k_scan_rows<<<(row_warps * 32 + 511) / 512, 512>>>(Mf, Mcn, Wvn, Wout);
    k_scan_cols<<<2048, TB>>>(bm, cm, S);

    // 3) gather remaining W_vn layers at shared pattern: thread per (l,k,i)
    k_gather_w<<<((NLAYER - 1) * CAP_VN * HH + TB - 1) / TB, TB>>>(Wvn);

    // 4) fused forward: one block per batch PAIR; bias rows computed in-block
    k_forward<<<BB / 2, FWD_TB, SM_TOTAL_BYTES>>>(x, out);
}

// round 9
// speedup vs baseline: 2.6754x; 1.0153x over previous
#include <cuda_runtime.h>
#include <math.h>
#include <stdint.h>

// Problem constants (fixed by the dataset)
#define BB 256
#define NN 768
#define HH 3072
#define NLAYER 19          // hidden VN/CN iterations
#define NSMAT 20           // S has 20 slices
#define CLIPV 0.999999f

// Sparsity capacities (actual: W_vn<=3, M_cn<=7, M_first<=7, W_out<=4, bm/cm/S col = 1)
#define CAP_VN 3
#define CAP_CN 7
#define CAP_F  7
#define CAP_OUT 4
#define CAP_S  4

// ---------------- device scratch (static; no allocation) ----------------
__device__ unsigned short g_f_idx16[CAP_F * HH];            // [k][i], pad -> NN (==1.0 sentinel)
__device__ __align__(16) unsigned short g_cn_pack[HH * 8];  // [i][8], pad -> HH (==1.0 sentinel)
__device__ __align__(8)  unsigned short g_vn_pack[HH * 4];  // [i][4]: j0,j1,j2,bias_idx
__device__ int            g_vn_cnt[HH];
__device__ float4         g_vn_val4[NLAYER][HH];            // (v0,v1,v2,-) per node
__device__ unsigned short g_out_idx16[CAP_OUT * NN];        // [k][n], pad -> 0 (val 0)
__device__ float          g_out_val  [CAP_OUT * NN];
__device__ float          g_bval  [HH];
__device__ unsigned short g_cmidx16[NN];
__device__ float          g_cmval  [NN];

__device__ int   g_s_idx[NSMAT * NN * CAP_S];
__device__ int   g_s_cnt[NSMAT * NN];
__device__ float g_s_val[NSMAT * NN * CAP_S];

// ---------------- helpers ----------------
__device__ __forceinline__ float atanh2f(float x) {
    // 2*atanh(clip(x)) = ln2*(log2(1+x) - log2(1-x))
    x = fminf(fmaxf(x, -CLIPV), CLIPV);
    return 0.69314718055994531f * (__log2f(1.0f + x) - __log2f(1.0f - x));
}
__device__ __forceinline__ float tanh_fast(float y) {
    // stable for all y: exp overflow -> inf -> __fdividef(2,inf)=0 -> result 1
    return 1.0f - __fdividef(2.0f, 1.0f + __expf(2.0f * y));
}

// pipelined float4 row scan: independent ballots + prefetch; emit(pos,col,val)
template <class F>
__device__ __forceinline__ int scan_row_f4(const float* __restrict__ row,
                                           int cols, int lane, F emit) {
    const float4* r4 = reinterpret_cast<const float4*>(row);
    const int nIter = cols / 128;           // 128 floats per warp-iteration
    unsigned below = (1u << lane) - 1u;
    int c = 0;
    float4 v = r4[lane];
    for (int it = 0; it < nIter; it++) {
        float4 vn = v;
        if (it + 1 < nIter) vn = r4[(it + 1) * 32 + lane];
        unsigned m0 = __ballot_sync(0xffffffffu, v.x != 0.0f);
        unsigned m1 = __ballot_sync(0xffffffffu, v.y != 0.0f);
        unsigned m2 = __ballot_sync(0xffffffffu, v.z != 0.0f);
        unsigned m3 = __ballot_sync(0xffffffffu, v.w != 0.0f);
        int c0 = c;
        int c1 = c0 + __popc(m0);
        int c2 = c1 + __popc(m1);
        int c3 = c2 + __popc(m2);
        int col0 = (it * 32 + lane) * 4;
        if (v.x != 0.0f) emit(c0 + __popc(m0 & below), col0 + 0, v.x);
        if (v.y != 0.0f) emit(c1 + __popc(m1 & below), col0 + 1, v.y);
        if (v.z != 0.0f) emit(c2 + __popc(m2 & below), col0 + 2, v.z);
        if (v.w != 0.0f) emit(c3 + __popc(m3 & below), col0 + 3, v.w);
        c = c3 + __popc(m3);
        v = vn;
    }
    return c;
}

// ---------------- setup kernels ----------------
__global__ void k_zero() {
    int t = blockIdx.x * blockDim.x + threadIdx.x;
    if (t < HH)         { g_bval[t] = 0.0f; g_vn_pack[t * 4 + 3] = 0; }
    if (t < NN)         { g_cmidx16[t] = 0; g_cmval[t] = 0.0f; }
    if (t < NSMAT * NN) g_s_cnt[t] = 0;
}

// merged row scans: Mf | Mcn | Wvn layer0 | Wout, one warp per row
__global__ void k_scan_rows(const float* __restrict__ Mf,
                            const float* __restrict__ Mcn,
                            const float* __restrict__ Wvn,
                            const float* __restrict__ Wout) {
    int gw = (blockIdx.x * blockDim.x + threadIdx.x) >> 5;
    int lane = threadIdx.x & 31;

    if (gw < HH) {                                    // Mf [HH x NN]
        int w = gw;
        int c = scan_row_f4(Mf + (size_t)w * NN, NN, lane,
            [&](int p, int col, float) { if (p < CAP_F) g_f_idx16[p * HH + w] = (unsigned short)col; });
        if (c > CAP_F) c = CAP_F;
        if (lane >= c && lane < CAP_F) g_f_idx16[lane * HH + w] = (unsigned short)NN;
    } else if (gw < 2 * HH) {                         // Mcn [HH x HH]
        int w = gw - HH;
        int c = scan_row_f4(Mcn + (size_t)w * HH, HH, lane,
            [&](int p, int col, float) { if (p < CAP_CN) g_cn_pack[w * 8 + p] = (unsigned short)col; });
        if (c > CAP_CN) c = CAP_CN;
        if (lane >= c && lane < 8) g_cn_pack[w * 8 + lane] = (unsigned short)HH;
    } else if (gw < 3 * HH) {                         // Wvn layer 0 [HH x HH]
        int w = gw - 2 * HH;
        float* vb = (float*)&g_vn_val4[0][0];
        int c = scan_row_f4(Wvn + (size_t)w * HH, HH, lane,
            [&](int p, int col, float v) {
                if (p < CAP_VN) { g_vn_pack[w * 4 + p] = (unsigned short)col; vb[w * 4 + p] = v; } });
        if (c > CAP_VN) c = CAP_VN;
        if (lane >= c && lane < CAP_VN) g_vn_pack[w * 4 + lane] = 0;   // slot 3 = bias idx, untouched
        if (lane >= c && lane < 4)      vb[w * 4 + lane] = 0.0f;       // zero val pads + w comp
        if (lane == 0) g_vn_cnt[w] = c;
    } else if (gw < 3 * HH + NN) {                    // Wout [NN x HH]
        int w = gw - 3 * HH;
        int c = scan_row_f4(Wout + (size_t)w * HH, HH, lane,
            [&](int p, int col, float v) {
                if (p < CAP_OUT) { g_out_idx16[p * NN + w] = (unsigned short)col; g_out_val[p * NN + w] = v; } });
        if (c > CAP_OUT) c = CAP_OUT;
        if (lane >= c && lane < CAP_OUT) { g_out_idx16[lane * NN + w] = 0; g_out_val[lane * NN + w] = 0.0f; }
    }
}

// merged column scans: bm (1 nz/col), cm (1 nz/col), S (atomic append)
__global__ void k_scan_cols(const float* __restrict__ bm,
                            const float* __restrict__ cm,
                            const float* __restrict__ S) {
    int tid = blockIdx.x * blockDim.x + threadIdx.x;
    int stride = gridDim.x * blockDim.x;

    const float4* b4 = reinterpret_cast<const float4*>(bm);
    for (int t = tid; t < NN * HH / 4; t += stride) {
        float4 v = b4[t];
        float a[4] = {v.x, v.y, v.z, v.w};
        #pragma unroll
        for (int s = 0; s < 4; s++) if (a[s] != 0.0f) {
            int f = t * 4 + s, col = f % HH, row = f / HH;
            g_bval[col] = a[s];
            g_vn_pack[col * 4 + 3] = (unsigned short)row;   // bias idx in slot 3
        }
    }
    const float4* c4 = reinterpret_cast<const float4*>(cm);
    for (int t = tid; t < NN * NN / 4; t += stride) {
        float4 v = c4[t];
        float a[4] = {v.x, v.y, v.z, v.w};
        #pragma unroll
        for (int s = 0; s < 4; s++) if (a[s] != 0.0f) {
            int f = t * 4 + s, col = f % NN, row = f / NN;
            g_cmval[col] = a[s];
            g_cmidx16[col] = (unsigned short)row;
        }
    }
    const float4* s4 = reinterpret_cast<const float4*>(S);
    for (int t = tid; t < NSMAT * NN * NN / 4; t += stride) {
        float4 v = s4[t];
        float a[4] = {v.x, v.y, v.z, v.w};
        #pragma unroll
        for (int s = 0; s < 4; s++) if (a[s] != 0.0f) {
            int f = t * 4 + s;
            int c = f % NN, r = (f / NN) % NN, l = f / (NN * NN);
            int colI = l * NN + c;
            int pos = atomicAdd(&g_s_cnt[colI], 1);
            if (pos < CAP_S) { g_s_idx[colI * CAP_S + pos] = r; g_s_val[colI * CAP_S + pos] = a[s]; }
        }
    }
}

// gather W_vn for layers 1..18: thread = (layer, k, node)
__global__ void k_gather_w(const float* __restrict__ W) {
    int t = blockIdx.x * blockDim.x + threadIdx.x;
    if (t >= (NLAYER - 1) * CAP_VN * HH) return;
    int i = t % HH;
    int r = t / HH;
    int k = r % CAP_VN;
    int l = r / CAP_VN + 1;
    float v = 0.0f;
    if (k < g_vn_cnt[i])
        v = W[(size_t)l * HH * HH + (size_t)i * HH + g_vn_pack[i * 4 + k]];
    ((float*)&g_vn_val4[l][i])[k] = v;
}

// ---------------- fused forward: one block per PAIR of batch elements ----------------
#define FWD_TB 1024
#define NODES_PER_T (HH / FWD_TB)   // 3

// smem: uint4 cpk[HH] | uint2 vpk[HH] | float2 su2[HH] | float2 sv2[HH+1] | float2 sw2[NN] | float2 sx2[NN]
#define SM_TOTAL_BYTES (HH * 16 + HH * 8 + HH * 8 + (HH + 1) * 8 + NN * 8 + NN * 8)  // 135176

__global__ void __launch_bounds__(FWD_TB)
k_forward(const float* __restrict__ x, float* __restrict__ out) {
    extern __shared__ char smem[];
    uint4*  cpk = (uint4*)smem;                // [HH] packed CN idx (8 u16)
    uint2*  vpk = (uint2*)(cpk + HH);          // [HH] packed VN idx (3 u16 + bias idx)
    float2* su2 = (float2*)(vpk + HH);         // [HH]     state u, both batches
    float2* sv2 = su2 + HH;                    // [HH+1]   state v, sv2[HH]=1.0 sentinel
    float2* sw2 = sv2 + HH + 1;                // [NN]     bias row, both batches
    float2* sx2 = sw2 + NN;                    // [NN]     channel LLR rows

    const int b0 = blockIdx.x * 2;
    const int b1 = b0 + 1;
    const int t = threadIdx.x;

    // stage packed indices (vectorized, L2-broadcast)
    const uint4* gc = (const uint4*)g_cn_pack;
    const uint2* gv = (const uint2*)g_vn_pack;
    for (int z = t; z < HH; z += FWD_TB) { cpk[z] = gc[z]; vpk[z] = gv[z]; }
    // x rows + channel tanh into sv2 (first CN input)
    for (int n = t; n < NN; n += FWD_TB) {
        float x0 = x[b0 * NN + n], x1 = x[b1 * NN + n];
        sx2[n] = make_float2(x0, x1);
        sv2[n] = make_float2(tanh_fast(0.5f * x0), tanh_fast(0.5f * x1));
    }
    // multiplicative-identity pad sentinels (no zero-skip logic needed)
    if (t == NN)  sv2[NN] = make_float2(1.0f, 1.0f);   // first-CN pad sentinel
    if (t == 0)   sv2[HH] = make_float2(1.0f, 1.0f);   // CN-loop pad sentinel (never overwritten)

    float bv_[NODES_PER_T];
    #pragma unroll
    for (int q = 0; q < NODES_PER_T; q++) bv_[q] = g_bval[t + FWD_TB * q];
    __syncthreads();

    // bias row for layer 0: T[0][b][n] = sum_m x[b][m]*S[0][m][n] (sparse, ~1 nz)
    for (int n = t; n < NN; n += FWD_TB) {
        int ln = n;                                    // l=0
        int c = g_s_cnt[ln]; if (c > CAP_S) c = CAP_S;
        float a0 = 0.0f, a1 = 0.0f;
        for (int k = 0; k < c; k++) {
            float sv_ = g_s_val[ln * CAP_S + k];
            float2 xx = sx2[g_s_idx[ln * CAP_S + k]];
            a0 += sv_ * xx.x; a1 += sv_ * xx.y;
        }
        sw2[n] = make_float2(a0, a1);
    }

    // first CN: u = 2*atanh(clip(prod tanh(0.5 x) over M_first row))
    #pragma unroll
    for (int q = 0; q < NODES_PER_T; q++) {
        int i = t + FWD_TB * q;
        float p0 = 1.0f, p1 = 1.0f;
        #pragma unroll
        for (int k = 0; k < CAP_F; k++) {
            float2 vv = sv2[g_f_idx16[k * HH + i]];    // pad -> sv2[NN]=1 -> identity
            p0 *= vv.x; p1 *= vv.y;
        }
        su2[i] = make_float2(atanh2f(p0), atanh2f(p1));
    }
    __syncthreads();

    // 19 BP iterations, 2 syncs per layer
    for (int l = 0; l < NLAYER; l++) {
        // VN: v = tanh(0.5*(W u + bias))
        #pragma unroll
        for (int q = 0; q < NODES_PER_T; q++) {
            int i = t + FWD_TB * q;
            uint2 p = vpk[i];
            int j0 = p.x & 0xffff, j1 = p.x >> 16, j2 = p.y & 0xffff, jb = p.y >> 16;
            float4 w4 = g_vn_val4[l][i];               // LDG.128, L2/L1 resident
            float2 u0 = su2[j0], u1 = su2[j1], u2 = su2[j2], tb = sw2[jb];
            float a0 = bv_[q] * tb.x + w4.x * u0.x + w4.y * u1.x + w4.z * u2.x;
            float a1 = bv_[q] * tb.y + w4.x * u0.y + w4.y * u1.y + w4.z * u2.y;
            sv2[i] = make_float2(tanh_fast(0.5f * a0), tanh_fast(0.5f * a1));
        }
        __syncthreads();

        // compute next layer's bias row (CN never reads sw2; VN done reading it)
        for (int n = t; n < NN; n += FWD_TB) {
            int ln = (l + 1) * NN + n;
            int c = g_s_cnt[ln]; if (c > CAP_S) c = CAP_S;
            float a0 = 0.0f, a1 = 0.0f;
            for (int k = 0; k < c; k++) {
                float sv_ = g_s_val[ln * CAP_S + k];
                float2 xx = sx2[g_s_idx[ln * CAP_S + k]];
                a0 += sv_ * xx.x; a1 += sv_ * xx.y;
            }
            sw2[n] = make_float2(a0, a1);
        }

        // CN fused with next atanh: pure 7-term product (pads read 1.0 sentinel)
        #pragma unroll
        for (int q = 0; q < NODES_PER_T; q++) {
            int i = t + FWD_TB * q;
            uint4 cw = cpk[i];
            int j0 = cw.x & 0xffff, j1 = cw.x >> 16,
                j2 = cw.y & 0xffff, j3 = cw.y >> 16,
                j4 = cw.z & 0xffff, j5 = cw.z >> 16,
                j6 = cw.w & 0xffff;                     // slot 7 always pad
            float2 v0 = sv2[j0], v1 = sv2[j1], v2 = sv2[j2], v3 = sv2[j3],
                   v4 = sv2[j4], v5 = sv2[j5], v6 = sv2[j6];
            float p0 = ((v0.x * v1.x) * (v2.x * v3.x)) * ((v4.x * v5.x) * v6.x);
            float p1 = ((v0.y * v1.y) * (v2.y * v3.y)) * ((v4.y * v5.y) * v6.y);
            su2[i] = make_float2(atanh2f(p0), atanh2f(p1));
        }
        __syncthreads();
    }

    // output: sigmoid(u @ W_out.T + T[19] @ channel_mask); sw2 == T[19] already
    for (int n = t; n < NN; n += FWD_TB) {
        float2 tb = sw2[g_cmidx16[n]];
        float a0 = g_cmval[n] * tb.x;
        float a1 = g_cmval[n] * tb.y;
        #pragma unroll
        for (int k = 0; k < CAP_OUT; k++) {
            float2 uu = su2[g_out_idx16[k * NN + n]];  // pad val=0
            float wv = g_out_val[k * NN + n];
            a0 += wv * uu.x;
            a1 += wv * uu.y;
        }
        out[b0 * NN + n] = __fdividef(1.0f, 1.0f + __expf(-a0));
        out[b1 * NN + n] = __fdividef(1.0f, 1.0f + __expf(-a1));
    }
}

// ---------------- launch ----------------
extern "C" void kernel_launch(void* const* d_in, const int* in_sizes, int n_in,
                              void* d_out, int out_size) {
    const float* x    = (const float*)d_in[0];   // [B,N]
    const float* Wvn  = (const float*)d_in[1];   // [19,H,H]
    const float* Wout = (const float*)d_in[2];   // [N,H]
    const float* S    = (const float*)d_in[3];   // [20,N,N]
    const float* bm   = (const float*)d_in[4];   // [N,H]
    const float* cm   = (const float*)d_in[5];   // [N,N]
    const float* Mf   = (const float*)d_in[6];   // [H,N]
    const float* Mcn  = (const float*)d_in[7];   // [H,H]
    float* out = (float*)d_out;

    const int TB = 256;

    // host-side attribute set (idempotent, cheap, outside capture semantics)
    cudaFuncSetAttribute(k_forward, cudaFuncAttributeMaxDynamicSharedMemorySize,
                         SM_TOTAL_BYTES);

    // 1) zero counters / defaults
    k_zero<<<(NSMAT * NN + TB - 1) / TB, TB>>>();

    // 2) merged vectorized scans (pipelined independent-ballot version)
    int row_warps = 3 * HH + NN;                            // 9984
    k_scan_rows<<<(row_warps * 32 + 511) / 512, 512>>>(Mf, Mcn, Wvn, Wout);
    k_scan_cols<<<2048, TB>>>(bm, cm, S);

    // 3) gather remaining W_vn layers at shared pattern: thread per (l,k,i)
    k_gather_w<<<((NLAYER - 1) * CAP_VN * HH + TB - 1) / TB, TB>>>(Wvn);

    // 4) fused forward: one block per batch PAIR; bias rows computed in-block
    k_forward<<<BB / 2, FWD_TB, SM_TOTAL_BYTES>>>(x, out);
}

// round 10
// speedup vs baseline: 2.7158x; 1.0151x over previous
#include <cuda_runtime.h>
#include <math.h>
#include <stdint.h>

// Problem constants (fixed by the dataset)
#define BB 256
#define NN 768
#define HH 3072
#define NLAYER 19          // hidden VN/CN iterations
#define NSMAT 20           // S has 20 slices
#define CLIPV 0.999999f

// Sparsity capacities (actual: W_vn<=3, M_cn<=7, M_first<=7, W_out<=4, bm/cm/S col = 1)
#define CAP_VN 3
#define CAP_CN 7
#define CAP_F  7
#define CAP_OUT 4
#define CAP_S  4

// ---------------- device scratch (static; no allocation) ----------------
__device__ unsigned short g_f_idx16[CAP_F * HH];            // [k][i], pad -> NN (==1.0 sentinel)
__device__ __align__(16) unsigned short g_cn_pack[HH * 8];  // [i][8], pad -> HH (==1.0 sentinel)
__device__ __align__(8)  unsigned short g_vn_pack[HH * 4];  // [i][4]: j0,j1,j2,bias_idx
__device__ int            g_vn_cnt[HH];
__device__ float4         g_vn_val4[NLAYER][HH];            // (v0,v1,v2,-) per node
__device__ unsigned short g_out_idx16[CAP_OUT * NN];        // [k][n], pad -> 0 (val 0)
__device__ float          g_out_val  [CAP_OUT * NN];
__device__ float          g_bval  [HH];
__device__ unsigned short g_cmidx16[NN];
__device__ float          g_cmval  [NN];

__device__ int   g_s_idx[NSMAT * NN * CAP_S];
__device__ int   g_s_cnt[NSMAT * NN];
__device__ float g_s_val[NSMAT * NN * CAP_S];

// ---------------- helpers ----------------
__device__ __forceinline__ float atanh2f(float x) {
    // 2*atanh(clip(x)) = ln2*(log2(1+x) - log2(1-x))
    x = fminf(fmaxf(x, -CLIPV), CLIPV);
    return 0.69314718055994531f * (__log2f(1.0f + x) - __log2f(1.0f - x));
}
__device__ __forceinline__ float tanh_fast(float y) {
    // stable for all y: exp overflow -> inf -> __fdividef(2,inf)=0 -> result 1
    return 1.0f - __fdividef(2.0f, 1.0f + __expf(2.0f * y));
}

// pipelined float4 row scan: independent ballots + prefetch; emit(pos,col,val)
template <class F>
__device__ __forceinline__ int scan_row_f4(const float* __restrict__ row,
                                           int cols, int lane, F emit) {
    const float4* r4 = reinterpret_cast<const float4*>(row);
    const int nIter = cols / 128;           // 128 floats per warp-iteration
    unsigned below = (1u << lane) - 1u;
    int c = 0;
    float4 v = r4[lane];
    for (int it = 0; it < nIter; it++) {
        float4 vn = v;
        if (it + 1 < nIter) vn = r4[(it + 1) * 32 + lane];
        unsigned m0 = __ballot_sync(0xffffffffu, v.x != 0.0f);
        unsigned m1 = __ballot_sync(0xffffffffu, v.y != 0.0f);
        unsigned m2 = __ballot_sync(0xffffffffu, v.z != 0.0f);
        unsigned m3 = __ballot_sync(0xffffffffu, v.w != 0.0f);
        int c0 = c;
        int c1 = c0 + __popc(m0);
        int c2 = c1 + __popc(m1);
        int c3 = c2 + __popc(m2);
        int col0 = (it * 32 + lane) * 4;
        if (v.x != 0.0f) emit(c0 + __popc(m0 & below), col0 + 0, v.x);
        if (v.y != 0.0f) emit(c1 + __popc(m1 & below), col0 + 1, v.y);
        if (v.z != 0.0f) emit(c2 + __popc(m2 & below), col0 + 2, v.z);
        if (v.w != 0.0f) emit(c3 + __popc(m3 & below), col0 + 3, v.w);
        c = c3 + __popc(m3);
        v = vn;
    }
    return c;
}

// ---------------- setup kernels ----------------
__global__ void k_zero() {
    int t = blockIdx.x * blockDim.x + threadIdx.x;
    if (t < HH)         { g_bval[t] = 0.0f; g_vn_pack[t * 4 + 3] = 0; }
    if (t < NN)         { g_cmidx16[t] = 0; g_cmval[t] = 0.0f; }
    if (t < NSMAT * NN) g_s_cnt[t] = 0;
}

// merged row scans: Mf | Mcn | Wvn layer0 | Wout, one warp per row
__global__ void k_scan_rows(const float* __restrict__ Mf,
                            const float* __restrict__ Mcn,
                            const float* __restrict__ Wvn,
                            const float* __restrict__ Wout) {
    int gw = (blockIdx.x * blockDim.x + threadIdx.x) >> 5;
    int lane = threadIdx.x & 31;

    if (gw < HH) {                                    // Mf [HH x NN]
        int w = gw;
        int c = scan_row_f4(Mf + (size_t)w * NN, NN, lane,
            [&](int p, int col, float) { if (p < CAP_F) g_f_idx16[p * HH + w] = (unsigned short)col; });
        if (c > CAP_F) c = CAP_F;
        if (lane >= c && lane < CAP_F) g_f_idx16[lane * HH + w] = (unsigned short)NN;
    } else if (gw < 2 * HH) {                         // Mcn [HH x HH]
        int w = gw - HH;
        int c = scan_row_f4(Mcn + (size_t)w * HH, HH, lane,
            [&](int p, int col, float) { if (p < CAP_CN) g_cn_pack[w * 8 + p] = (unsigned short)col; });
        if (c > CAP_CN) c = CAP_CN;
        if (lane >= c && lane < 8) g_cn_pack[w * 8 + lane] = (unsigned short)HH;
    } else if (gw < 3 * HH) {                         // Wvn layer 0 [HH x HH]
        int w = gw - 2 * HH;
        float* vb = (float*)&g_vn_val4[0][0];
        int c = scan_row_f4(Wvn + (size_t)w * HH, HH, lane,
            [&](int p, int col, float v) {
                if (p < CAP_VN) { g_vn_pack[w * 4 + p] = (unsigned short)col; vb[w * 4 + p] = v; } });
        if (c > CAP_VN) c = CAP_VN;
        if (lane >= c && lane < CAP_VN) g_vn_pack[w * 4 + lane] = 0;   // slot 3 = bias idx, untouched
        if (lane >= c && lane < 4)      vb[w * 4 + lane] = 0.0f;       // zero val pads + w comp
        if (lane == 0) g_vn_cnt[w] = c;
    } else if (gw < 3 * HH + NN) {                    // Wout [NN x HH]
        int w = gw - 3 * HH;
        int c = scan_row_f4(Wout + (size_t)w * HH, HH, lane,
            [&](int p, int col, float v) {
                if (p < CAP_OUT) { g_out_idx16[p * NN + w] = (unsigned short)col; g_out_val[p * NN + w] = v; } });
        if (c > CAP_OUT) c = CAP_OUT;
        if (lane >= c && lane < CAP_OUT) { g_out_idx16[lane * NN + w] = 0; g_out_val[lane * NN + w] = 0.0f; }
    }
}

// merged column scans: bm (1 nz/col), cm (1 nz/col), S (atomic append)
__global__ void k_scan_cols(const float* __restrict__ bm,
                            const float* __restrict__ cm,
                            const float* __restrict__ S) {
    int tid = blockIdx.x * blockDim.x + threadIdx.x;
    int stride = gridDim.x * blockDim.x;

    const float4* b4 = reinterpret_cast<const float4*>(bm);
    for (int t = tid; t < NN * HH / 4; t += stride) {
        float4 v = b4[t];
        float a[4] = {v.x, v.y, v.z, v.w};
        #pragma unroll
        for (int s = 0; s < 4; s++) if (a[s] != 0.0f) {
            int f = t * 4 + s, col = f % HH, row = f / HH;
            g_bval[col] = a[s];
            g_vn_pack[col * 4 + 3] = (unsigned short)row;   // bias idx in slot 3
        }
    }
    const float4* c4 = reinterpret_cast<const float4*>(cm);
    for (int t = tid; t < NN * NN / 4; t += stride) {
        float4 v = c4[t];
        float a[4] = {v.x, v.y, v.z, v.w};
        #pragma unroll
        for (int s = 0; s < 4; s++) if (a[s] != 0.0f) {
            int f = t * 4 + s, col = f % NN, row = f / NN;
            g_cmval[col] = a[s];
            g_cmidx16[col] = (unsigned short)row;
        }
    }
    const float4* s4 = reinterpret_cast<const float4*>(S);
    for (int t = tid; t < NSMAT * NN * NN / 4; t += stride) {
        float4 v = s4[t];
        float a[4] = {v.x, v.y, v.z, v.w};
        #pragma unroll
        for (int s = 0; s < 4; s++) if (a[s] != 0.0f) {
            int f = t * 4 + s;
            int c = f % NN, r = (f / NN) % NN, l = f / (NN * NN);
            int colI = l * NN + c;
            int pos = atomicAdd(&g_s_cnt[colI], 1);
            if (pos < CAP_S) { g_s_idx[colI * CAP_S + pos] = r; g_s_val[colI * CAP_S + pos] = a[s]; }
        }
    }
}

// gather W_vn for layers 1..18: thread = (layer, k, node)
__global__ void k_gather_w(const float* __restrict__ W) {
    int t = blockIdx.x * blockDim.x + threadIdx.x;
    if (t >= (NLAYER - 1) * CAP_VN * HH) return;
    int i = t % HH;
    int r = t / HH;
    int k = r % CAP_VN;
    int l = r / CAP_VN + 1;
    float v = 0.0f;
    if (k < g_vn_cnt[i])
        v = W[(size_t)l * HH * HH + (size_t)i * HH + g_vn_pack[i * 4 + k]];
    ((float*)&g_vn_val4[l][i])[k] = v;
}

// ---------------- fused forward: one block per PAIR of batch elements ----------------
#define FWD_TB 1024
#define NODES_PER_T (HH / FWD_TB)   // 3

// smem: float2 su2[HH] | float2 sv2[HH+1] | float2 sw2[NN] | float2 sx2[NN]
#define SM_TOTAL_BYTES (HH * 8 + (HH + 1) * 8 + NN * 8 + NN * 8)   // 61448

__global__ void __launch_bounds__(FWD_TB)
k_forward(const float* __restrict__ x, float* __restrict__ out) {
    extern __shared__ char smem[];
    float2* su2 = (float2*)smem;               // [HH]     state u, both batches
    float2* sv2 = su2 + HH;                    // [HH+1]   state v, sv2[HH]=1.0 sentinel
    float2* sw2 = sv2 + HH + 1;                // [NN]     bias row, both batches
    float2* sx2 = sw2 + NN;                    // [NN]     channel LLR rows

    const int b0 = blockIdx.x * 2;
    const int b1 = b0 + 1;
    const int t = threadIdx.x;

    // layer-invariant indices/bias live in REGISTERS for all 19 layers
    // (coalesced LDG.128/LDG.64 once; removes 74KB/layer of smem traffic)
    uint4 cw_[NODES_PER_T];
    uint2 vp_[NODES_PER_T];
    float bv_[NODES_PER_T];
    #pragma unroll
    for (int q = 0; q < NODES_PER_T; q++) {
        int i = t + FWD_TB * q;
        cw_[q] = ((const uint4*)g_cn_pack)[i];
        vp_[q] = ((const uint2*)g_vn_pack)[i];
        bv_[q] = g_bval[i];
    }

    // x rows + channel tanh into sv2 (first CN input)
    for (int n = t; n < NN; n += FWD_TB) {
        float x0 = x[b0 * NN + n], x1 = x[b1 * NN + n];
        sx2[n] = make_float2(x0, x1);
        sv2[n] = make_float2(tanh_fast(0.5f * x0), tanh_fast(0.5f * x1));
    }
    // multiplicative-identity pad sentinels (no zero-skip logic needed)
    if (t == NN)  sv2[NN] = make_float2(1.0f, 1.0f);   // first-CN pad sentinel
    if (t == 0)   sv2[HH] = make_float2(1.0f, 1.0f);   // CN-loop pad sentinel (never overwritten)
    __syncthreads();

    // bias row for layer 0: T[0][b][n] = sum_m x[b][m]*S[0][m][n] (sparse, ~1 nz)
    for (int n = t; n < NN; n += FWD_TB) {
        int ln = n;                                    // l=0
        int c = g_s_cnt[ln]; if (c > CAP_S) c = CAP_S;
        float a0 = 0.0f, a1 = 0.0f;
        for (int k = 0; k < c; k++) {
            float sv_ = g_s_val[ln * CAP_S + k];
            float2 xx = sx2[g_s_idx[ln * CAP_S + k]];
            a0 += sv_ * xx.x; a1 += sv_ * xx.y;
        }
        sw2[n] = make_float2(a0, a1);
    }

    // first CN: u = 2*atanh(clip(prod tanh(0.5 x) over M_first row))
    #pragma unroll
    for (int q = 0; q < NODES_PER_T; q++) {
        int i = t + FWD_TB * q;
        float p0 = 1.0f, p1 = 1.0f;
        #pragma unroll
        for (int k = 0; k < CAP_F; k++) {
            float2 vv = sv2[g_f_idx16[k * HH + i]];    // pad -> sv2[NN]=1 -> identity
            p0 *= vv.x; p1 *= vv.y;
        }
        su2[i] = make_float2(atanh2f(p0), atanh2f(p1));
    }
    __syncthreads();

    // 19 BP iterations, 2 syncs per layer
    for (int l = 0; l < NLAYER; l++) {
        // VN: v = tanh(0.5*(W u + bias))
        #pragma unroll
        for (int q = 0; q < NODES_PER_T; q++) {
            int i = t + FWD_TB * q;
            uint2 p = vp_[q];
            int j0 = p.x & 0xffff, j1 = p.x >> 16, j2 = p.y & 0xffff, jb = p.y >> 16;
            float4 w4 = g_vn_val4[l][i];               // LDG.128, L2/L1 resident
            float2 u0 = su2[j0], u1 = su2[j1], u2 = su2[j2], tb = sw2[jb];
            float a0 = bv_[q] * tb.x + w4.x * u0.x + w4.y * u1.x + w4.z * u2.x;
            float a1 = bv_[q] * tb.y + w4.x * u0.y + w4.y * u1.y + w4.z * u2.y;
            sv2[i] = make_float2(tanh_fast(0.5f * a0), tanh_fast(0.5f * a1));
        }
        __syncthreads();

        // compute next layer's bias row (CN never reads sw2; VN done reading it)
        for (int n = t; n < NN; n += FWD_TB) {
            int ln = (l + 1) * NN + n;
            int c = g_s_cnt[ln]; if (c > CAP_S) c = CAP_S;
            float a0 = 0.0f, a1 = 0.0f;
            for (int k = 0; k < c; k++) {
                float sv_ = g_s_val[ln * CAP_S + k];
                float2 xx = sx2[g_s_idx[ln * CAP_S + k]];
                a0 += sv_ * xx.x; a1 += sv_ * xx.y;
            }
            sw2[n] = make_float2(a0, a1);
        }

        // CN fused with next atanh: pure 7-term product (pads read 1.0 sentinel)
        #pragma unroll
        for (int q = 0; q < NODES_PER_T; q++) {
            int i = t + FWD_TB * q;
            uint4 cw = cw_[q];
            int j0 = cw.x & 0xffff, j1 = cw.x >> 16,
                j2 = cw.y & 0xffff, j3 = cw.y >> 16,
                j4 = cw.z & 0xffff, j5 = cw.z >> 16,
                j6 = cw.w & 0xffff;                     // slot 7 always pad
            float2 v0 = sv2[j0], v1 = sv2[j1], v2 = sv2[j2], v3 = sv2[j3],
                   v4 = sv2[j4], v5 = sv2[j5], v6 = sv2[j6];
            float p0 = ((v0.x * v1.x) * (v2.x * v3.x)) * ((v4.x * v5.x) * v6.x);
            float p1 = ((v0.y * v1.y) * (v2.y * v3.y)) * ((v4.y * v5.y) * v6.y);
            su2[i] = make_float2(atanh2f(p0), atanh2f(p1));
        }
        __syncthreads();
    }

    // output: sigmoid(u @ W_out.T + T[19] @ channel_mask); sw2 == T[19] already
    for (int n = t; n < NN; n += FWD_TB) {
        float2 tb = sw2[g_cmidx16[n]];
        float a0 = g_cmval[n] * tb.x;
        float a1 = g_cmval[n] * tb.y;
        #pragma unroll
        for (int k = 0; k < CAP_OUT; k++) {
            float2 uu = su2[g_out_idx16[k * NN + n]];  // pad val=0
            float wv = g_out_val[k * NN + n];
            a0 += wv * uu.x;
            a1 += wv * uu.y;
        }
        out[b0 * NN + n] = __fdividef(1.0f, 1.0f + __expf(-a0));
        out[b1 * NN + n] = __fdividef(1.0f, 1.0f + __expf(-a1));
    }
}

// ---------------- launch ----------------
extern "C" void kernel_launch(void* const* d_in, const int* in_sizes, int n_in,
                              void* d_out, int out_size) {
    const float* x    = (const float*)d_in[0];   // [B,N]
    const float* Wvn  = (const float*)d_in[1];   // [19,H,H]
    const float* Wout = (const float*)d_in[2];   // [N,H]
    const float* S    = (const float*)d_in[3];   // [20,N,N]
    const float* bm   = (const float*)d_in[4];   // [N,H]
    const float* cm   = (const float*)d_in[5];   // [N,N]
    const float* Mf   = (const float*)d_in[6];   // [H,N]
    const float* Mcn  = (const float*)d_in[7];   // [H,H]
    float* out = (float*)d_out;

    const int TB = 256;

    // host-side attribute set (idempotent, cheap, outside capture semantics)
    cudaFuncSetAttribute(k_forward, cudaFuncAttributeMaxDynamicSharedMemorySize,
                         SM_TOTAL_BYTES);

    // 1) zero counters / defaults
    k_zero<<<(NSMAT * NN + TB - 1) / TB, TB>>>();

    // 2) merged vectorized scans (pipelined independent-ballot version)
    int row_warps = 3 * HH + NN;                            // 9984
    k_scan_rows<<<(row_warps * 32 + 511) / 512, 512>>>(Mf, Mcn, Wvn, Wout);
    k_scan_cols<<<2048, TB>>>(bm, cm, S);

    // 3) gather remaining W_vn layers at shared pattern: thread per (l,k,i)
    k_gather_w<<<((NLAYER - 1) * CAP_VN * HH + TB - 1) / TB, TB>>>(Wvn);

    // 4) fused forward: one block per batch PAIR; indices live in registers
    k_forward<<<BB / 2, FWD_TB, SM_TOTAL_BYTES>>>(x, out);
}